// round 14
// baseline (speedup 1.0000x reference)
#include <cuda_runtime.h>
#include <cuda_bf16.h>
#include <mma.h>
#include <stdint.h>
#include <math.h>

using namespace nvcuda;

#define NA   8000
#define NRES 2000
#define KNN_K 15
#define NE   (NA*KNN_K)        // 120000
#define NANG 9998
#define EPAD (938*128)         // 120064 padded edge rows
#define NTILE_E 938
#define NTILE_A 79
#define SP  136                // smem bf16 row stride
#define SPF 20                 // float scratch row stride

#define GDIM 16
#define NCELL (GDIM*GDIM*GDIM)   // 4096
#define GOX  (-48.0f)
#define GH   6.0f
#define GINV (1.0f/6.0f)
#define FULLM 0xffffffffu

typedef unsigned long long ull;
typedef unsigned int u32;

__device__ __forceinline__ float fast_tanh(float x) {
    float y; asm("tanh.approx.f32 %0, %1;" : "=f"(y) : "f"(x)); return y;
}

// ---------------------------------------------------------------------------
// scratch
// ---------------------------------------------------------------------------
__device__ float g_coords[NA*3];
__device__ float g_vels[NA*3];
__device__ float g_accs[NA*3];
__device__ float g_tf[NA*3];
__device__ float g_aacc[NA*3];
__device__ int   g_nbr[NE];
__device__ float g_nd[NE*3];
__device__ float g_P[8064*128];
__device__ float g_Q[8064*128];
__device__ float g_A1[8064*128];
__device__ float g_geom[NANG*8];
__device__ __align__(16) __nv_bfloat16 g_H1b[(size_t)NTILE_E*128*128];
__device__ __align__(16) __nv_bfloat16 g_W2b[128*128];
__device__ __align__(16) __nv_bfloat16 g_W3b[128*128];
__device__ __align__(16) __nv_bfloat16 g_aW2b[128*128];

// spatial grid (fixed bounds [-48,48]^3, 16^3 cells, h = 6.0 exact)
__device__ int  g_cellCount[NCELL];   // invariant: zero between builds
__device__ int  g_cellFill[NCELL];
__device__ int  g_cellStart[NCELL];
__device__ int  g_atomCell[NA];
__device__ int  g_done = 0;
__device__ __align__(16) float4 g_pos4[NA];
__device__ __align__(16) float4 g_spos4[NA];   // cell-sorted (x,y,z,id-bits)

__device__ __forceinline__ int cell_clamp(float v) {
    return min(GDIM-1, max(0, (int)((v - GOX) * GINV)));
}

// ---------------------------------------------------------------------------
// init + loss
// ---------------------------------------------------------------------------
__global__ void init_loss_kernel(const float* __restrict__ coords,
                                 const float* __restrict__ vels,
                                 const float* __restrict__ temp,
                                 const float* __restrict__ dtp,
                                 float* __restrict__ out_loss) {
    __shared__ float red[256];
    if (blockIdx.x < 94) {
        int i = blockIdx.x*256 + threadIdx.x;
        if (i < NA*3) {
            g_coords[i] = coords[i];
            g_vels[i]   = vels[i] * temp[0];
            g_accs[i]   = 0.0f;
        }
        return;
    }
    float T = temp[0], dt = dtp[0];
    float s = 0.0f;
    for (int i = threadIdx.x; i < NA*3; i += 256) {
        float c = coords[i];
        float x = ((vels[i]*T)*dt)*3.0f;
        float r = (c + x) - c;
        s += r*r;
    }
    red[threadIdx.x] = s; __syncthreads();
    for (int o = 128; o > 0; o >>= 1) {
        if (threadIdx.x < o) red[threadIdx.x] += red[threadIdx.x+o];
        __syncthreads();
    }
    if (threadIdx.x == 0) out_loss[0] = sqrtf(red[0] / (float)NA);
}

// ---------------------------------------------------------------------------
// pos update + full grid build
// ---------------------------------------------------------------------------
__global__ void pos_build_kernel(const float* __restrict__ dtp, int flag) {
    int t = threadIdx.x;
    int i = blockIdx.x*256 + t;                 // 32*256 = 8192
    float dt = dtp[0];
    if (i < NA) {
        float x = g_coords[3*i+0] + g_vels[3*i+0]*dt + 0.5f*g_accs[3*i+0]*dt*dt;
        float y = g_coords[3*i+1] + g_vels[3*i+1]*dt + 0.5f*g_accs[3*i+1]*dt*dt;
        float z = g_coords[3*i+2] + g_vels[3*i+2]*dt + 0.5f*g_accs[3*i+2]*dt*dt;
        g_coords[3*i+0] = x; g_coords[3*i+1] = y; g_coords[3*i+2] = z;
        g_pos4[i] = make_float4(x, y, z, 0.0f);
        g_aacc[3*i+0] = 0.f; g_aacc[3*i+1] = 0.f; g_aacc[3*i+2] = 0.f;
        g_tf[3*i+0] = 0.f;  g_tf[3*i+1] = 0.f;  g_tf[3*i+2] = 0.f;
        if (flag) {
            int c = (cell_clamp(z)*GDIM + cell_clamp(y))*GDIM + cell_clamp(x);
            g_atomCell[i] = c;
            atomicAdd(&g_cellCount[c], 1);
        }
    }
    if (!flag) return;

    __threadfence();
    __shared__ int last;
    if (t == 0) last = (atomicAdd(&g_done, 1) == (int)gridDim.x - 1);
    __syncthreads();
    if (!last) return;

    __shared__ int part[256];
    int base = t*16;
    int loc[16], s = 0;
#pragma unroll
    for (int k = 0; k < 16; ++k) { loc[k] = g_cellCount[base+k]; s += loc[k]; }
    part[t] = s; __syncthreads();
    for (int off = 1; off < 256; off <<= 1) {
        int v = (t >= off) ? part[t-off] : 0;
        __syncthreads();
        part[t] += v;
        __syncthreads();
    }
    int ex = part[t] - s;
#pragma unroll
    for (int k = 0; k < 16; ++k) { g_cellStart[base+k] = ex; ex += loc[k]; }
    __syncthreads();

    for (int a = t; a < NA; a += 256) {
        int c = g_atomCell[a];
        int p = g_cellStart[c] + atomicAdd(&g_cellFill[c], 1);
        float4 v = g_pos4[a];
        v.w = __int_as_float(a);
        g_spos4[p] = v;
    }
    __syncthreads();
#pragma unroll
    for (int k = 0; k < 16; ++k) { g_cellCount[base+k] = 0; g_cellFill[base+k] = 0; }
    if (t == 0) g_done = 0;
}

// ---------------------------------------------------------------------------
// angle indexing
// ---------------------------------------------------------------------------
struct AngleInfo { int u1, u2, u3, ct; };
__device__ __forceinline__ AngleInfo angle_info(int inst) {
    AngleInfo ai; int r;
    if (inst < 2000)      { r = inst;       ai.u1=4*r;   ai.u2=4*r+1; ai.u3=4*r+2; ai.ct=4*r+1; }
    else if (inst < 3999) { r = inst-2000;  ai.u1=4*r+1; ai.u2=4*r+2; ai.u3=4*r+4; ai.ct=4*r+2; }
    else if (inst < 5998) { r = inst-3999;  ai.u1=4*r+2; ai.u2=4*r+4; ai.u3=4*r+5; ai.ct=4*r+4; }
    else if (inst < 7998) { r = inst-5998;  ai.u1=4*r;   ai.u2=4*r+1; ai.u3=4*r+3; ai.ct=4*r+1; }
    else                  { r = inst-7998;  ai.u1=4*r+2; ai.u2=4*r+1; ai.u3=4*r+3; ai.ct=4*r+1; }
    return ai;
}

// ---------------------------------------------------------------------------
// COMBO: blocks [0, NTILE_A) = fused angle path; rest = KNN (4 lanes/query).
// KNN selection: UNSORTED register top-16 with tracked max (cheap insert),
// exact ring bound = min over lanes of (full ? lane-max : inf), final
// bitonic sort + 2 reverse-merge rounds.
// ---------------------------------------------------------------------------
#define SM_COMBO (34816*2 + 10240 + 1024)
__global__ void __launch_bounds__(256, 2)
combo_kernel(const float* __restrict__ aW1,
             const float* __restrict__ ab2, const float* __restrict__ aW3,
             const float* __restrict__ ab3) {
    extern __shared__ char sm[];
    int tid = threadIdx.x;

    if (blockIdx.x >= NTILE_A) {
        // ================= KNN path =================
        int kbid = blockIdx.x - NTILE_A;
        int p = (kbid*256 + tid) >> 2;
        int quarter = tid & 3;
        u32 grpmask = 0xFu << ((tid & 31) & ~3);

        float4 qp = g_spos4[p];
        int q = __float_as_int(qp.w);
        int cx = cell_clamp(qp.x), cy = cell_clamp(qp.y), cz = cell_clamp(qp.z);

        ull best[16];
#pragma unroll
        for (int k = 0; k < 16; ++k) best[k] = ~0ull;
        ull maxv = ~0ull;
        int maxi = 0;

        int segrot = 0;
        auto scan_run = [&](int c0, int c1) {
            int st = g_cellStart[c0];
            int en = (c1 == NCELL-1) ? NA : g_cellStart[c1+1];
            int b0 = st + ((quarter + segrot) & 3);
            ++segrot;
            for (int ii = b0; ii < en; ii += 4) {
                float4 pt = g_spos4[ii];
                float dx = qp.x - pt.x, dy = qp.y - pt.y, dz = qp.z - pt.z;
                float d2 = dx*dx + dy*dy + dz*dz;
                ull key = ((ull)__float_as_uint(d2) << 32) | (u32)__float_as_int(pt.w);
                if (key < maxv) {
                    best[maxi] = key;
                    maxv = best[0]; maxi = 0;
#pragma unroll
                    for (int t = 1; t < 16; ++t)
                        if (best[t] > maxv) { maxv = best[t]; maxi = t; }
                }
            }
        };

        for (int r = 0; r < GDIM; ++r) {
            int z0 = max(cz-r, 0), z1 = min(cz+r, GDIM-1);
            for (int zz = z0; zz <= z1; ++zz) {
                bool fz = (zz == cz-r) || (zz == cz+r);
                int y0 = max(cy-r, 0), y1 = min(cy+r, GDIM-1);
                for (int yy = y0; yy <= y1; ++yy) {
                    bool face = fz || (yy == cy-r) || (yy == cy+r);
                    int rb = (zz*GDIM + yy)*GDIM;
                    if (face) {
                        int x0 = max(cx-r, 0), x1 = min(cx+r, GDIM-1);
                        scan_run(rb + x0, rb + x1);
                    } else {
                        if (cx-r >= 0)      scan_run(rb + cx-r, rb + cx-r);
                        if (cx+r <= GDIM-1) scan_run(rb + cx+r, rb + cx+r);
                    }
                }
            }
            // union-16th upper bound: any full lane's max bounds the union's
            // 16th (its 16 keys are a subset). maxv==~0 <=> lane not full.
            ull ub = maxv;
#pragma unroll
            for (int o = 1; o <= 2; o <<= 1) {
                ull t = __shfl_xor_sync(grpmask, ub, o);
                ub = (ub < t) ? ub : t;
            }
            if (ub != ~0ull) {
                float td2 = __uint_as_float((u32)(ub >> 32));
                float bnd = GH * (float)r;
                if (td2 <= bnd*bnd*0.9999f) break;
            }
        }

        // one-time bitonic sort (ascending) of the 16 register keys
#pragma unroll
        for (int k = 2; k <= 16; k <<= 1) {
#pragma unroll
            for (int j = k >> 1; j > 0; j >>= 1) {
#pragma unroll
                for (int i2 = 0; i2 < 16; ++i2) {
                    int l = i2 ^ j;
                    if (l > i2) {
                        bool up = ((i2 & k) == 0);
                        ull a = best[i2], b = best[l];
                        bool sw = up ? (a > b) : (a < b);
                        best[i2] = sw ? b : a;
                        best[l]  = sw ? a : b;
                    }
                }
            }
        }

        // two merge rounds (disjoint candidate sets): reverse-merge + clean
#pragma unroll
        for (int o = 1; o <= 2; o <<= 1) {
            ull other[16];
#pragma unroll
            for (int k = 0; k < 16; ++k)
                other[k] = __shfl_xor_sync(grpmask, best[k], o);
            ull c[16];
#pragma unroll
            for (int k = 0; k < 16; ++k) {
                ull a = best[k], b = other[15-k];
                c[k] = (a < b) ? a : b;
            }
#pragma unroll
            for (int j = 8; j > 0; j >>= 1) {
#pragma unroll
                for (int i2 = 0; i2 < 16; ++i2) {
                    if ((i2 & j) == 0) {
                        int pr = i2 | j;
                        ull lo = c[i2], hi = c[pr];
                        c[i2] = (lo < hi) ? lo : hi;
                        c[pr] = (lo < hi) ? hi : lo;
                    }
                }
            }
#pragma unroll
            for (int k = 0; k < 16; ++k) best[k] = c[k];
        }

        if (quarter == 0) {
#pragma unroll
            for (int k = 1; k < 16; ++k)
                g_nbr[q*KNN_K + k - 1] = (int)(u32)best[k];
        }
        return;
    }

    // ================= fused angle path =================
    __nv_bfloat16* sA = (__nv_bfloat16*)sm;
    __nv_bfloat16* sW = (__nv_bfloat16*)(sm + 34816);
    float*        ssc = (float*)(sm + 69632);
    float*       sab2 = (float*)(sm + 79872);
    float*       saw3 = sab2 + 128;
    int w = tid >> 5, lane = tid & 31;
    int n0 = lane*4;

    {
        const uint4* gW = (const uint4*)g_aW2b;
        for (int i = tid; i < 2048; i += 256) {
            int row = i >> 4, c8 = i & 15;
            *(uint4*)&sW[row*SP + c8*8] = gW[i];
        }
        if (tid < 128) { sab2[tid] = ab2[tid]; saw3[tid] = aW3[tid]; }
    }

    // geom + layer1 -> sA (one warp per row, 16 iterations)
    {
        float4 w24 = *(const float4*)&aW1[24*128 + n0];
        int i0 = blockIdx.x*128;
#pragma unroll 1
        for (int it = 0; it < 16; ++it) {
            int row = it*8 + w;
            int inst = i0 + row;
            uint2 v = make_uint2(0u, 0u);
            if (inst < NANG) {
                AngleInfo ai = angle_info(inst);
                float bax = g_coords[ai.u1*3+0] - g_coords[ai.u2*3+0];
                float bay = g_coords[ai.u1*3+1] - g_coords[ai.u2*3+1];
                float baz = g_coords[ai.u1*3+2] - g_coords[ai.u2*3+2];
                float bcx = g_coords[ai.u3*3+0] - g_coords[ai.u2*3+0];
                float bcy = g_coords[ai.u3*3+1] - g_coords[ai.u2*3+1];
                float bcz = g_coords[ai.u3*3+2] - g_coords[ai.u2*3+2];
                float ba_n = sqrtf(bax*bax + bay*bay + baz*baz);
                float bc_n = sqrtf(bcx*bcx + bcy*bcy + bcz*bcz);
                float cosang = (bax*bcx + bay*bcy + baz*bcz) / (ba_n * bc_n);
                cosang = fminf(fmaxf(cosang, -1.0f + 1e-6f), 1.0f - 1e-6f);
                float ang = acosf(cosang);
                if (lane == 0) {
                    g_geom[inst*8+0]=bax; g_geom[inst*8+1]=bay; g_geom[inst*8+2]=baz;
                    g_geom[inst*8+3]=bcx; g_geom[inst*8+4]=bcy; g_geom[inst*8+5]=bcz;
                }
                float4 a1 = *(const float4*)&g_A1[ai.ct*128 + n0];
                float h0 = fast_tanh(a1.x + ang*w24.x);
                float h1 = fast_tanh(a1.y + ang*w24.y);
                float h2 = fast_tanh(a1.z + ang*w24.z);
                float h3 = fast_tanh(a1.w + ang*w24.w);
                __nv_bfloat162 p0 = __floats2bfloat162_rn(h0, h1);
                __nv_bfloat162 p1 = __floats2bfloat162_rn(h2, h3);
                v.x = *(u32*)&p0; v.y = *(u32*)&p1;
            }
            *(uint2*)&sA[row*SP + n0] = v;
        }
    }
    __syncthreads();

    float* sc = ssc + w*(16*SPF);
    int r = lane >> 1, ch = (lane & 1)*8;

    wmma::fragment<wmma::accumulator,16,16,16,float> acc[8];
#pragma unroll
    for (int f = 0; f < 8; ++f) wmma::fill_fragment(acc[f], 0.0f);
#pragma unroll
    for (int kt = 0; kt < 8; ++kt) {
        wmma::fragment<wmma::matrix_a,16,16,16,__nv_bfloat16,wmma::row_major> af;
        wmma::load_matrix_sync(af, &sA[(w*16)*SP + kt*16], SP);
#pragma unroll
        for (int f = 0; f < 8; ++f) {
            wmma::fragment<wmma::matrix_b,16,16,16,__nv_bfloat16,wmma::row_major> bf;
            wmma::load_matrix_sync(bf, &sW[(kt*16)*SP + f*16], SP);
            wmma::mma_sync(acc[f], af, bf, acc[f]);
        }
    }

    float s = 0.0f;
#pragma unroll
    for (int f = 0; f < 8; ++f) {
        wmma::store_matrix_sync(sc, acc[f], SPF, wmma::mem_row_major);
        __syncwarp();
#pragma unroll
        for (int c = 0; c < 8; ++c) {
            int n = f*16 + ch + c;
            s += fast_tanh(sc[r*SPF + ch + c] + sab2[n]) * saw3[n];
        }
        __syncwarp();
    }
    s += __shfl_xor_sync(FULLM, s, 1);

    if ((lane & 1) == 0) {
        int inst = blockIdx.x*128 + w*16 + r;
        if (inst < NANG) {
            float af_ = s + ab3[0];
            AngleInfo ai = angle_info(inst);
            float bax=g_geom[inst*8+0], bay=g_geom[inst*8+1], baz=g_geom[inst*8+2];
            float bcx=g_geom[inst*8+3], bcy=g_geom[inst*8+4], bcz=g_geom[inst*8+5];
            float ba_n = sqrtf(bax*bax + bay*bay + baz*baz);
            float bc_n = sqrtf(bcx*bcx + bcy*bcy + bcz*bcz);
            float crx = bay*bcz - baz*bcy;
            float cry = baz*bcx - bax*bcz;
            float crz = bax*bcy - bay*bcx;
            float v1x = bay*crz - baz*cry;
            float v1y = baz*crx - bax*crz;
            float v1z = bax*cry - bay*crx;
            float n1 = fmaxf(sqrtf(v1x*v1x + v1y*v1y + v1z*v1z), 1e-12f);
            float v2x = -(bcy*crz - bcz*cry);
            float v2y = -(bcz*crx - bcx*crz);
            float v2z = -(bcx*cry - bcy*crx);
            float n2 = fmaxf(sqrtf(v2x*v2x + v2y*v2y + v2z*v2z), 1e-12f);
            float fax = af_*(v1x/n1)/ba_n, fay = af_*(v1y/n1)/ba_n, faz = af_*(v1z/n1)/ba_n;
            float fcx = af_*(v2x/n2)/bc_n, fcy = af_*(v2y/n2)/bc_n, fcz = af_*(v2z/n2)/bc_n;
            atomicAdd(&g_aacc[ai.u1*3+0], fax);
            atomicAdd(&g_aacc[ai.u1*3+1], fay);
            atomicAdd(&g_aacc[ai.u1*3+2], faz);
            atomicAdd(&g_aacc[ai.u2*3+0], -fax - fcx);
            atomicAdd(&g_aacc[ai.u2*3+1], -fay - fcy);
            atomicAdd(&g_aacc[ai.u2*3+2], -faz - fcz);
            atomicAdd(&g_aacc[ai.u3*3+0], fcx);
            atomicAdd(&g_aacc[ai.u3*3+1], fcy);
            atomicAdd(&g_aacc[ai.u3*3+2], fcz);
        }
    }
}

// ---------------------------------------------------------------------------
// integration tail
// ---------------------------------------------------------------------------
__global__ void finalize_kernel(const float* __restrict__ masses,
                                const float* __restrict__ dtp) {
    int i = blockIdx.x*blockDim.x + threadIdx.x;
    if (i >= NA) return;
    float m = masses[i], dt = dtp[0];
#pragma unroll
    for (int d = 0; d < 3; ++d) {
        float tf  = g_tf[i*3+d] / 100.0f;
        float acc = tf / m + g_aacc[i*3+d] / (m*100.0f);
        float al  = g_accs[i*3+d];
        g_vels[i*3+d] += 0.5f*(al + acc)*dt;
        g_accs[i*3+d]  = acc;
    }
}

__global__ void writeout_kernel(float* __restrict__ out) {
    int i = blockIdx.x*blockDim.x + threadIdx.x;
    if (i < NA*3) out[i] = g_coords[i];
}

// ---------------------------------------------------------------------------
// one-time precompute
// ---------------------------------------------------------------------------
__device__ void gemm128_dev(const float* __restrict__ A,
                            const float* __restrict__ W,
                            const float* __restrict__ bias,
                            float* __restrict__ C,
                            int M, int K, int fuse, int bm) {
    __shared__ float Ast[16][128];
    __shared__ float Ws [16][128];
    int tid = threadIdx.x;
    int tm = tid >> 4, tn = tid & 15;

    float acc[8][8];
#pragma unroll
    for (int i = 0; i < 8; ++i)
#pragma unroll
        for (int j = 0; j < 8; ++j) acc[i][j] = 0.0f;

    int arow = tid >> 1;
    int acol = (tid & 1) * 8;
    int wrow = tid >> 4;
    int wcol = (tid & 15) * 8;

    for (int kk = 0; kk < K; kk += 16) {
        {
            int grow = bm + arow;
            float4 v0 = make_float4(0,0,0,0), v1 = make_float4(0,0,0,0);
            if (grow < M && (kk + acol) < K) {
                const float* ap = A + (size_t)grow*K + kk + acol;
                v0 = *(const float4*)ap;
                v1 = *(const float4*)(ap + 4);
            }
            Ast[acol+0][arow] = v0.x; Ast[acol+1][arow] = v0.y;
            Ast[acol+2][arow] = v0.z; Ast[acol+3][arow] = v0.w;
            Ast[acol+4][arow] = v1.x; Ast[acol+5][arow] = v1.y;
            Ast[acol+6][arow] = v1.z; Ast[acol+7][arow] = v1.w;
        }
        {
            int gk = kk + wrow;
            float4 v0 = make_float4(0,0,0,0), v1 = make_float4(0,0,0,0);
            if (gk < K) {
                const float* wp = W + (size_t)gk*128 + wcol;
                v0 = *(const float4*)wp;
                v1 = *(const float4*)(wp + 4);
            }
            *(float4*)&Ws[wrow][wcol]   = v0;
            *(float4*)&Ws[wrow][wcol+4] = v1;
        }
        __syncthreads();
#pragma unroll
        for (int k2 = 0; k2 < 16; ++k2) {
            float4 a0 = *(const float4*)&Ast[k2][tm*8];
            float4 a1 = *(const float4*)&Ast[k2][tm*8+4];
            float4 w0 = *(const float4*)&Ws[k2][tn*8];
            float4 w1 = *(const float4*)&Ws[k2][tn*8+4];
            float av[8] = {a0.x,a0.y,a0.z,a0.w,a1.x,a1.y,a1.z,a1.w};
            float wv[8] = {w0.x,w0.y,w0.z,w0.w,w1.x,w1.y,w1.z,w1.w};
#pragma unroll
            for (int i = 0; i < 8; ++i)
#pragma unroll
                for (int j = 0; j < 8; ++j)
                    acc[i][j] += av[i]*wv[j];
        }
        __syncthreads();
    }
    float bv[8] = {0,0,0,0,0,0,0,0};
    if (fuse >= 1) {
        float4 b0 = *(const float4*)&bias[tn*8];
        float4 b1 = *(const float4*)&bias[tn*8+4];
        bv[0]=b0.x; bv[1]=b0.y; bv[2]=b0.z; bv[3]=b0.w;
        bv[4]=b1.x; bv[5]=b1.y; bv[6]=b1.z; bv[7]=b1.w;
    }
#pragma unroll
    for (int i = 0; i < 8; ++i) {
        int m = bm + tm*8 + i;
        if (m < M) {
            float o[8];
#pragma unroll
            for (int j = 0; j < 8; ++j) o[j] = acc[i][j] + bv[j];
            *(float4*)&C[(size_t)m*128 + tn*8]     = make_float4(o[0],o[1],o[2],o[3]);
            *(float4*)&C[(size_t)m*128 + tn*8 + 4] = make_float4(o[4],o[5],o[6],o[7]);
        }
    }
}

__global__ void precompute_kernel(const float* __restrict__ node_f,
                                  const float* __restrict__ dW1,
                                  const float* __restrict__ aW1,
                                  const float* __restrict__ ab1,
                                  const float* __restrict__ dW2,
                                  const float* __restrict__ dW3,
                                  const float* __restrict__ aW2) {
    int y = blockIdx.y;
    if (blockIdx.x == 63) {
        const float* src = (y == 0) ? dW2 : (y == 1) ? dW3 : aW2;
        __nv_bfloat16* dst = (y == 0) ? g_W2b : (y == 1) ? g_W3b : g_aW2b;
        for (int idx = threadIdx.x; idx < 128*128; idx += 256)
            dst[idx] = __float2bfloat16(src[idx]);
        return;
    }
    int bm = blockIdx.x * 128;
    if (y == 0)      gemm128_dev(node_f, dW1,          nullptr, g_P,  NA, 24, 0, bm);
    else if (y == 1) gemm128_dev(node_f, dW1 + 24*128, nullptr, g_Q,  NA, 24, 0, bm);
    else             gemm128_dev(node_f, aW1,          ab1,     g_A1, NA, 24, 1, bm);
}

// ---------------------------------------------------------------------------
// edge layer 1 (gather) -> bf16 row-major tiles
// ---------------------------------------------------------------------------
__global__ void edge_h1_kernel(const float* __restrict__ dW1,
                               const float* __restrict__ db1) {
    int widx = threadIdx.x >> 5, lane = threadIdx.x & 31;
    int e = blockIdx.x*8 + widx;
    if (e >= EPAD) return;
    __nv_bfloat16* dst = g_H1b + (size_t)e*128 + lane*4;

    if (e >= NE) { *(uint2*)dst = make_uint2(0u, 0u); return; }

    int i = e / KNN_K;
    int j = g_nbr[e];
    float4 pi = g_pos4[i];
    float4 pj = g_pos4[j];
    float dx = pi.x - pj.x;
    float dy = pi.y - pj.y;
    float dz = pi.z - pj.z;
    float dist = sqrtf(dx*dx + dy*dy + dz*dz);
    float inv = 1.0f / fmaxf(dist, 0.01f);
    if (lane == 0) {
        g_nd[e*3+0] = dx*inv; g_nd[e*3+1] = dy*inv; g_nd[e*3+2] = dz*inv;
    }
    float seq = fminf(fabsf((float)(i >> 2) - (float)(j >> 2)) / 5.0f, 1.0f);

    int n0 = lane*4;
    float4 pp  = *(const float4*)&g_P[i*128 + n0];
    float4 qq  = *(const float4*)&g_Q[j*128 + n0];
    float4 w48 = *(const float4*)&dW1[48*128 + n0];
    float4 w49 = *(const float4*)&dW1[49*128 + n0];
    float4 b   = *(const float4*)&db1[n0];
    float h0 = fast_tanh(pp.x + qq.x + dist*w48.x + seq*w49.x + b.x);
    float h1 = fast_tanh(pp.y + qq.y + dist*w48.y + seq*w49.y + b.y);
    float h2 = fast_tanh(pp.z + qq.z + dist*w48.z + seq*w49.z + b.z);
    float h3 = fast_tanh(pp.w + qq.w + dist*w48.w + seq*w49.w + b.w);
    __nv_bfloat162 p0 = __floats2bfloat162_rn(h0, h1);
    __nv_bfloat162 p1 = __floats2bfloat162_rn(h2, h3);
    uint2 v; v.x = *(u32*)&p0; v.y = *(u32*)&p1;
    *(uint2*)dst = v;
}

// ---------------------------------------------------------------------------
// fused dist MLP (wmma bf16)
// ---------------------------------------------------------------------------
#define SM_DIST (34816*3 + 10240 + 1536)
__global__ void __launch_bounds__(256, 2)
fused_dist_kernel(const float* __restrict__ db2, const float* __restrict__ db3,
                  const float* __restrict__ dW4, const float* __restrict__ db4) {
    extern __shared__ char sm[];
    __nv_bfloat16* sA  = (__nv_bfloat16*)sm;
    __nv_bfloat16* sW2 = (__nv_bfloat16*)(sm + 34816);
    __nv_bfloat16* sW3 = (__nv_bfloat16*)(sm + 69632);
    float*         ssc = (float*)(sm + 104448);
    float*         sb2 = (float*)(sm + 114688);
    float*         sb3 = sb2 + 128;
    float*         sw4 = sb3 + 128;
    int tid = threadIdx.x, w = tid >> 5, lane = tid & 31;

    {
        const uint4* gA  = (const uint4*)(g_H1b + (size_t)blockIdx.x*16384);
        const uint4* gW2 = (const uint4*)g_W2b;
        const uint4* gW3 = (const uint4*)g_W3b;
        for (int i = tid; i < 2048; i += 256) {
            int row = i >> 4, c8 = i & 15;
            int d = row*SP + c8*8;
            *(uint4*)&sA[d]  = gA[i];
            *(uint4*)&sW2[d] = gW2[i];
            *(uint4*)&sW3[d] = gW3[i];
        }
        if (tid < 128) { sb2[tid] = db2[tid]; sb3[tid] = db3[tid]; sw4[tid] = dW4[tid]; }
    }
    __syncthreads();

    float* sc = ssc + w*(16*SPF);
    int r = lane >> 1, ch = (lane & 1)*8;

    wmma::fragment<wmma::accumulator,16,16,16,float> acc[8];

#pragma unroll
    for (int f = 0; f < 8; ++f) wmma::fill_fragment(acc[f], 0.0f);
#pragma unroll
    for (int kt = 0; kt < 8; ++kt) {
        wmma::fragment<wmma::matrix_a,16,16,16,__nv_bfloat16,wmma::row_major> af;
        wmma::load_matrix_sync(af, &sA[(w*16)*SP + kt*16], SP);
#pragma unroll
        for (int f = 0; f < 8; ++f) {
            wmma::fragment<wmma::matrix_b,16,16,16,__nv_bfloat16,wmma::row_major> bf;
            wmma::load_matrix_sync(bf, &sW2[(kt*16)*SP + f*16], SP);
            wmma::mma_sync(acc[f], af, bf, acc[f]);
        }
    }
#pragma unroll
    for (int f = 0; f < 8; ++f) {
        wmma::store_matrix_sync(sc, acc[f], SPF, wmma::mem_row_major);
        __syncwarp();
        float v[8];
#pragma unroll
        for (int c = 0; c < 8; ++c)
            v[c] = fast_tanh(sc[r*SPF + ch + c] + sb2[f*16 + ch + c]);
        __nv_bfloat162 q0 = __floats2bfloat162_rn(v[0], v[1]);
        __nv_bfloat162 q1 = __floats2bfloat162_rn(v[2], v[3]);
        __nv_bfloat162 q2 = __floats2bfloat162_rn(v[4], v[5]);
        __nv_bfloat162 q3 = __floats2bfloat162_rn(v[6], v[7]);
        uint4 pk; pk.x = *(u32*)&q0; pk.y = *(u32*)&q1; pk.z = *(u32*)&q2; pk.w = *(u32*)&q3;
        *(uint4*)&sA[(w*16 + r)*SP + f*16 + ch] = pk;
        __syncwarp();
    }

#pragma unroll
    for (int f = 0; f < 8; ++f) wmma::fill_fragment(acc[f], 0.0f);
#pragma unroll
    for (int kt = 0; kt < 8; ++kt) {
        wmma::fragment<wmma::matrix_a,16,16,16,__nv_bfloat16,wmma::row_major> af;
        wmma::load_matrix_sync(af, &sA[(w*16)*SP + kt*16], SP);
#pragma unroll
        for (int f = 0; f < 8; ++f) {
            wmma::fragment<wmma::matrix_b,16,16,16,__nv_bfloat16,wmma::row_major> bf;
            wmma::load_matrix_sync(bf, &sW3[(kt*16)*SP + f*16], SP);
            wmma::mma_sync(acc[f], af, bf, acc[f]);
        }
    }
    float s = 0.0f;
#pragma unroll
    for (int f = 0; f < 8; ++f) {
        wmma::store_matrix_sync(sc, acc[f], SPF, wmma::mem_row_major);
        __syncwarp();
#pragma unroll
        for (int c = 0; c < 8; ++c) {
            int n = f*16 + ch + c;
            s += fast_tanh(sc[r*SPF + ch + c] + sb3[n]) * sw4[n];
        }
        __syncwarp();
    }
    s += __shfl_xor_sync(FULLM, s, 1);

    if ((lane & 1) == 0) {
        int e = blockIdx.x*128 + w*16 + r;
        if (e < NE) {
            s += db4[0];
            int a = e / KNN_K;
            atomicAdd(&g_tf[a*3+0], s * g_nd[e*3+0]);
            atomicAdd(&g_tf[a*3+1], s * g_nd[e*3+1]);
            atomicAdd(&g_tf[a*3+2], s * g_nd[e*3+2]);
        }
    }
}

// ---------------------------------------------------------------------------
// host launcher
// ---------------------------------------------------------------------------
extern "C" void kernel_launch(void* const* d_in, const int* in_sizes, int n_in,
                              void* d_out, int out_size) {
    const float* coords = (const float*)d_in[0];
    const float* node_f = (const float*)d_in[1];
    const float* masses = (const float*)d_in[3];
    const float* vels   = (const float*)d_in[4];
    const float* dW1 = (const float*)d_in[5];
    const float* db1 = (const float*)d_in[6];
    const float* dW2 = (const float*)d_in[7];
    const float* db2 = (const float*)d_in[8];
    const float* dW3 = (const float*)d_in[9];
    const float* db3 = (const float*)d_in[10];
    const float* dW4 = (const float*)d_in[11];
    const float* db4 = (const float*)d_in[12];
    const float* aW1 = (const float*)d_in[13];
    const float* ab1 = (const float*)d_in[14];
    const float* aW2 = (const float*)d_in[15];
    const float* ab2 = (const float*)d_in[16];
    const float* aW3 = (const float*)d_in[17];
    const float* ab3 = (const float*)d_in[18];
    const float* dtp  = (const float*)d_in[20];
    const float* temp = (const float*)d_in[21];
    float* out = (float*)d_out;

    cudaFuncSetAttribute(fused_dist_kernel, cudaFuncAttributeMaxDynamicSharedMemorySize, SM_DIST);
    cudaFuncSetAttribute(combo_kernel,      cudaFuncAttributeMaxDynamicSharedMemorySize, SM_COMBO);

    init_loss_kernel<<<95, 256>>>(coords, vels, temp, dtp, out + (out_size - 1));   // 0
    precompute_kernel<<<dim3(64,3), 256>>>(node_f, dW1, aW1, ab1, dW2, dW3, aW2);   // 1

    for (int s = 0; s < 3; ++s) {
        pos_build_kernel<<<32, 256>>>(dtp, s < 2 ? 1 : 0);                          // 2
        if (s == 2) break;

        combo_kernel<<<NTILE_A + 125, 256, SM_COMBO>>>(aW1, ab2, aW3, ab3);         // 3 <- ncu
        edge_h1_kernel<<<EPAD/8, 256>>>(dW1, db1);
        fused_dist_kernel<<<NTILE_E, 256, SM_DIST>>>(db2, db3, dW4, db4);
        finalize_kernel<<<32, 256>>>(masses, dtp);
    }

    writeout_kernel<<<94, 256>>>(out);
}

// round 15
// speedup vs baseline: 1.1244x; 1.1244x over previous
#include <cuda_runtime.h>
#include <cuda_bf16.h>
#include <mma.h>
#include <stdint.h>
#include <math.h>

using namespace nvcuda;

#define NA   8000
#define NRES 2000
#define KNN_K 15
#define NE   (NA*KNN_K)        // 120000
#define NANG 9998
#define EPAD (938*128)         // 120064 padded edge rows
#define NTILE_E 938
#define NTILE_A 79
#define SP  136                // smem bf16 row stride
#define SPF 20                 // float scratch row stride

#define GDIM 24
#define NCELL (GDIM*GDIM*GDIM)   // 13824
#define GOX  (-48.0f)
#define GH   4.0f
#define GINV (0.25f)
#define FULLM 0xffffffffu

typedef unsigned long long ull;
typedef unsigned int u32;

__device__ __forceinline__ float fast_tanh(float x) {
    float y; asm("tanh.approx.f32 %0, %1;" : "=f"(y) : "f"(x)); return y;
}

// ---------------------------------------------------------------------------
// scratch
// ---------------------------------------------------------------------------
__device__ float g_coords[NA*3];
__device__ float g_vels[NA*3];
__device__ float g_accs[NA*3];
__device__ float g_tf[NA*3];
__device__ float g_aacc[NA*3];
__device__ int   g_nbr[NE];
__device__ float g_nd[NE*3];
__device__ float g_P[8064*128];
__device__ float g_Q[8064*128];
__device__ float g_A1[8064*128];
__device__ float g_geom[NANG*8];
__device__ __align__(16) __nv_bfloat16 g_H1b[(size_t)NTILE_E*128*128];
__device__ __align__(16) __nv_bfloat16 g_W2b[128*128];
__device__ __align__(16) __nv_bfloat16 g_W3b[128*128];
__device__ __align__(16) __nv_bfloat16 g_aW2b[128*128];

// spatial grid (fixed bounds [-48,48]^3, 24^3 cells, h = 4.0 exact)
__device__ int  g_cellCount[NCELL];   // invariant: zero between builds
__device__ int  g_cellFill[NCELL];
__device__ int  g_cellStart[NCELL];
__device__ int  g_atomCell[NA];
__device__ int  g_done = 0;
__device__ __align__(16) float4 g_pos4[NA];
__device__ __align__(16) float4 g_spos4[NA];   // cell-sorted (x,y,z,id-bits)

__device__ __forceinline__ int cell_clamp(float v) {
    return min(GDIM-1, max(0, (int)((v - GOX) * GINV)));
}

// ---------------------------------------------------------------------------
// init + loss
// ---------------------------------------------------------------------------
__global__ void init_loss_kernel(const float* __restrict__ coords,
                                 const float* __restrict__ vels,
                                 const float* __restrict__ temp,
                                 const float* __restrict__ dtp,
                                 float* __restrict__ out_loss) {
    __shared__ float red[256];
    if (blockIdx.x < 94) {
        int i = blockIdx.x*256 + threadIdx.x;
        if (i < NA*3) {
            g_coords[i] = coords[i];
            g_vels[i]   = vels[i] * temp[0];
            g_accs[i]   = 0.0f;
        }
        return;
    }
    float T = temp[0], dt = dtp[0];
    float s = 0.0f;
    for (int i = threadIdx.x; i < NA*3; i += 256) {
        float c = coords[i];
        float x = ((vels[i]*T)*dt)*3.0f;
        float r = (c + x) - c;
        s += r*r;
    }
    red[threadIdx.x] = s; __syncthreads();
    for (int o = 128; o > 0; o >>= 1) {
        if (threadIdx.x < o) red[threadIdx.x] += red[threadIdx.x+o];
        __syncthreads();
    }
    if (threadIdx.x == 0) out_loss[0] = sqrtf(red[0] / (float)NA);
}

// ---------------------------------------------------------------------------
// pos update + full grid build
// ---------------------------------------------------------------------------
__global__ void pos_build_kernel(const float* __restrict__ dtp, int flag) {
    int t = threadIdx.x;
    int i = blockIdx.x*256 + t;                 // 32*256 = 8192
    float dt = dtp[0];
    if (i < NA) {
        float x = g_coords[3*i+0] + g_vels[3*i+0]*dt + 0.5f*g_accs[3*i+0]*dt*dt;
        float y = g_coords[3*i+1] + g_vels[3*i+1]*dt + 0.5f*g_accs[3*i+1]*dt*dt;
        float z = g_coords[3*i+2] + g_vels[3*i+2]*dt + 0.5f*g_accs[3*i+2]*dt*dt;
        g_coords[3*i+0] = x; g_coords[3*i+1] = y; g_coords[3*i+2] = z;
        g_pos4[i] = make_float4(x, y, z, 0.0f);
        g_aacc[3*i+0] = 0.f; g_aacc[3*i+1] = 0.f; g_aacc[3*i+2] = 0.f;
        g_tf[3*i+0] = 0.f;  g_tf[3*i+1] = 0.f;  g_tf[3*i+2] = 0.f;
        if (flag) {
            int c = (cell_clamp(z)*GDIM + cell_clamp(y))*GDIM + cell_clamp(x);
            g_atomCell[i] = c;
            atomicAdd(&g_cellCount[c], 1);
        }
    }
    if (!flag) return;

    __threadfence();
    __shared__ int last;
    if (t == 0) last = (atomicAdd(&g_done, 1) == (int)gridDim.x - 1);
    __syncthreads();
    if (!last) return;

    // --- single-block: scan 13824 counts (54/thread) -> starts, scatter ---
    __shared__ int part[256];
    int base = t*54;
    int s = 0;
    for (int k = 0; k < 54; ++k) s += g_cellCount[base+k];
    part[t] = s; __syncthreads();
    for (int off = 1; off < 256; off <<= 1) {
        int v = (t >= off) ? part[t-off] : 0;
        __syncthreads();
        part[t] += v;
        __syncthreads();
    }
    int ex = part[t] - s;
    for (int k = 0; k < 54; ++k) { g_cellStart[base+k] = ex; ex += g_cellCount[base+k]; }
    __syncthreads();

    for (int a = t; a < NA; a += 256) {
        int c = g_atomCell[a];
        int p = g_cellStart[c] + atomicAdd(&g_cellFill[c], 1);
        float4 v = g_pos4[a];
        v.w = __int_as_float(a);
        g_spos4[p] = v;
    }
    __syncthreads();
    for (int k = 0; k < 54; ++k) { g_cellCount[base+k] = 0; g_cellFill[base+k] = 0; }
    if (t == 0) g_done = 0;
}

// ---------------------------------------------------------------------------
// angle indexing
// ---------------------------------------------------------------------------
struct AngleInfo { int u1, u2, u3, ct; };
__device__ __forceinline__ AngleInfo angle_info(int inst) {
    AngleInfo ai; int r;
    if (inst < 2000)      { r = inst;       ai.u1=4*r;   ai.u2=4*r+1; ai.u3=4*r+2; ai.ct=4*r+1; }
    else if (inst < 3999) { r = inst-2000;  ai.u1=4*r+1; ai.u2=4*r+2; ai.u3=4*r+4; ai.ct=4*r+2; }
    else if (inst < 5998) { r = inst-3999;  ai.u1=4*r+2; ai.u2=4*r+4; ai.u3=4*r+5; ai.ct=4*r+4; }
    else if (inst < 7998) { r = inst-5998;  ai.u1=4*r;   ai.u2=4*r+1; ai.u3=4*r+3; ai.ct=4*r+1; }
    else                  { r = inst-7998;  ai.u1=4*r+2; ai.u2=4*r+1; ai.u3=4*r+3; ai.ct=4*r+1; }
    return ai;
}

// ---------------------------------------------------------------------------
// COMBO: blocks [0, NTILE_A) = fused angle path; rest = KNN (4 lanes/query,
// sorted-insert selection — static register indexing only).
// ---------------------------------------------------------------------------
#define SM_COMBO (34816*2 + 10240 + 1024)
__global__ void __launch_bounds__(256, 2)
combo_kernel(const float* __restrict__ aW1,
             const float* __restrict__ ab2, const float* __restrict__ aW3,
             const float* __restrict__ ab3) {
    extern __shared__ char sm[];
    int tid = threadIdx.x;

    if (blockIdx.x >= NTILE_A) {
        // ================= KNN path =================
        int kbid = blockIdx.x - NTILE_A;
        int p = (kbid*256 + tid) >> 2;
        int quarter = tid & 3;
        u32 grpmask = 0xFu << ((tid & 31) & ~3);

        float4 qp = g_spos4[p];
        int q = __float_as_int(qp.w);
        int cx = cell_clamp(qp.x), cy = cell_clamp(qp.y), cz = cell_clamp(qp.z);

        ull best[16];
#pragma unroll
        for (int k = 0; k < 16; ++k) best[k] = ~0ull;

        int segrot = 0;
        auto scan_run = [&](int c0, int c1) {
            int st = g_cellStart[c0];
            int en = (c1 == NCELL-1) ? NA : g_cellStart[c1+1];
            int b0 = st + ((quarter + segrot) & 3);
            ++segrot;
            for (int ii = b0; ii < en; ii += 4) {
                float4 pt = g_spos4[ii];
                float dx = qp.x - pt.x, dy = qp.y - pt.y, dz = qp.z - pt.z;
                float d2 = dx*dx + dy*dy + dz*dz;
                ull key = ((ull)__float_as_uint(d2) << 32) | (u32)__float_as_int(pt.w);
                if (key < best[15]) {
                    best[15] = key;
#pragma unroll
                    for (int tt = 15; tt > 0; --tt) {
                        ull a = best[tt-1], b = best[tt];
                        best[tt-1] = (a < b) ? a : b;
                        best[tt]   = (a < b) ? b : a;
                    }
                }
            }
        };

        for (int r = 0; r < GDIM; ++r) {
            int z0 = max(cz-r, 0), z1 = min(cz+r, GDIM-1);
            for (int zz = z0; zz <= z1; ++zz) {
                bool fz = (zz == cz-r) || (zz == cz+r);
                int y0 = max(cy-r, 0), y1 = min(cy+r, GDIM-1);
                for (int yy = y0; yy <= y1; ++yy) {
                    bool face = fz || (yy == cy-r) || (yy == cy+r);
                    int rb = (zz*GDIM + yy)*GDIM;
                    if (face) {
                        int x0 = max(cx-r, 0), x1 = min(cx+r, GDIM-1);
                        scan_run(rb + x0, rb + x1);
                    } else {
                        if (cx-r >= 0)      scan_run(rb + cx-r, rb + cx-r);
                        if (cx+r <= GDIM-1) scan_run(rb + cx+r, rb + cx+r);
                    }
                }
            }
            ull b3 = best[3], b15 = best[15];
#pragma unroll
            for (int o = 1; o <= 2; o <<= 1) {
                ull t3  = __shfl_xor_sync(grpmask, b3,  o);
                ull t15 = __shfl_xor_sync(grpmask, b15, o);
                b3  = (b3  > t3)  ? b3  : t3;
                b15 = (b15 < t15) ? b15 : t15;
            }
            ull ub = (b15 < b3) ? b15 : b3;
            if (ub != ~0ull) {
                float td2 = __uint_as_float((u32)(ub >> 32));
                float bnd = GH * (float)r;
                if (td2 <= bnd*bnd*0.9999f) break;
            }
        }

#pragma unroll
        for (int o = 1; o <= 2; o <<= 1) {
            ull other[16];
#pragma unroll
            for (int k = 0; k < 16; ++k)
                other[k] = __shfl_xor_sync(grpmask, best[k], o);
            ull c[16];
#pragma unroll
            for (int k = 0; k < 16; ++k) {
                ull a = best[k], b = other[15-k];
                c[k] = (a < b) ? a : b;
            }
#pragma unroll
            for (int j = 8; j > 0; j >>= 1) {
#pragma unroll
                for (int i2 = 0; i2 < 16; ++i2) {
                    if ((i2 & j) == 0) {
                        int pr = i2 | j;
                        ull lo = c[i2], hi = c[pr];
                        c[i2] = (lo < hi) ? lo : hi;
                        c[pr] = (lo < hi) ? hi : lo;
                    }
                }
            }
#pragma unroll
            for (int k = 0; k < 16; ++k) best[k] = c[k];
        }

        if (quarter == 0) {
#pragma unroll
            for (int k = 1; k < 16; ++k)
                g_nbr[q*KNN_K + k - 1] = (int)(u32)best[k];
        }
        return;
    }

    // ================= fused angle path =================
    __nv_bfloat16* sA = (__nv_bfloat16*)sm;
    __nv_bfloat16* sW = (__nv_bfloat16*)(sm + 34816);
    float*        ssc = (float*)(sm + 69632);
    float*       sab2 = (float*)(sm + 79872);
    float*       saw3 = sab2 + 128;
    int w = tid >> 5, lane = tid & 31;
    int n0 = lane*4;

    {
        const uint4* gW = (const uint4*)g_aW2b;
        for (int i = tid; i < 2048; i += 256) {
            int row = i >> 4, c8 = i & 15;
            *(uint4*)&sW[row*SP + c8*8] = gW[i];
        }
        if (tid < 128) { sab2[tid] = ab2[tid]; saw3[tid] = aW3[tid]; }
    }

    // geom + layer1 -> sA (one warp per row, 16 iterations)
    {
        float4 w24 = *(const float4*)&aW1[24*128 + n0];
        int i0 = blockIdx.x*128;
#pragma unroll 1
        for (int it = 0; it < 16; ++it) {
            int row = it*8 + w;
            int inst = i0 + row;
            uint2 v = make_uint2(0u, 0u);
            if (inst < NANG) {
                AngleInfo ai = angle_info(inst);
                float bax = g_coords[ai.u1*3+0] - g_coords[ai.u2*3+0];
                float bay = g_coords[ai.u1*3+1] - g_coords[ai.u2*3+1];
                float baz = g_coords[ai.u1*3+2] - g_coords[ai.u2*3+2];
                float bcx = g_coords[ai.u3*3+0] - g_coords[ai.u2*3+0];
                float bcy = g_coords[ai.u3*3+1] - g_coords[ai.u2*3+1];
                float bcz = g_coords[ai.u3*3+2] - g_coords[ai.u2*3+2];
                float ba_n = sqrtf(bax*bax + bay*bay + baz*baz);
                float bc_n = sqrtf(bcx*bcx + bcy*bcy + bcz*bcz);
                float cosang = (bax*bcx + bay*bcy + baz*bcz) / (ba_n * bc_n);
                cosang = fminf(fmaxf(cosang, -1.0f + 1e-6f), 1.0f - 1e-6f);
                float ang = acosf(cosang);
                if (lane == 0) {
                    g_geom[inst*8+0]=bax; g_geom[inst*8+1]=bay; g_geom[inst*8+2]=baz;
                    g_geom[inst*8+3]=bcx; g_geom[inst*8+4]=bcy; g_geom[inst*8+5]=bcz;
                }
                float4 a1 = *(const float4*)&g_A1[ai.ct*128 + n0];
                float h0 = fast_tanh(a1.x + ang*w24.x);
                float h1 = fast_tanh(a1.y + ang*w24.y);
                float h2 = fast_tanh(a1.z + ang*w24.z);
                float h3 = fast_tanh(a1.w + ang*w24.w);
                __nv_bfloat162 p0 = __floats2bfloat162_rn(h0, h1);
                __nv_bfloat162 p1 = __floats2bfloat162_rn(h2, h3);
                v.x = *(u32*)&p0; v.y = *(u32*)&p1;
            }
            *(uint2*)&sA[row*SP + n0] = v;
        }
    }
    __syncthreads();

    float* sc = ssc + w*(16*SPF);
    int r = lane >> 1, ch = (lane & 1)*8;

    wmma::fragment<wmma::accumulator,16,16,16,float> acc[8];
#pragma unroll
    for (int f = 0; f < 8; ++f) wmma::fill_fragment(acc[f], 0.0f);
#pragma unroll
    for (int kt = 0; kt < 8; ++kt) {
        wmma::fragment<wmma::matrix_a,16,16,16,__nv_bfloat16,wmma::row_major> af;
        wmma::load_matrix_sync(af, &sA[(w*16)*SP + kt*16], SP);
#pragma unroll
        for (int f = 0; f < 8; ++f) {
            wmma::fragment<wmma::matrix_b,16,16,16,__nv_bfloat16,wmma::row_major> bf;
            wmma::load_matrix_sync(bf, &sW[(kt*16)*SP + f*16], SP);
            wmma::mma_sync(acc[f], af, bf, acc[f]);
        }
    }

    float s = 0.0f;
#pragma unroll
    for (int f = 0; f < 8; ++f) {
        wmma::store_matrix_sync(sc, acc[f], SPF, wmma::mem_row_major);
        __syncwarp();
#pragma unroll
        for (int c = 0; c < 8; ++c) {
            int n = f*16 + ch + c;
            s += fast_tanh(sc[r*SPF + ch + c] + sab2[n]) * saw3[n];
        }
        __syncwarp();
    }
    s += __shfl_xor_sync(FULLM, s, 1);

    if ((lane & 1) == 0) {
        int inst = blockIdx.x*128 + w*16 + r;
        if (inst < NANG) {
            float af_ = s + ab3[0];
            AngleInfo ai = angle_info(inst);
            float bax=g_geom[inst*8+0], bay=g_geom[inst*8+1], baz=g_geom[inst*8+2];
            float bcx=g_geom[inst*8+3], bcy=g_geom[inst*8+4], bcz=g_geom[inst*8+5];
            float ba_n = sqrtf(bax*bax + bay*bay + baz*baz);
            float bc_n = sqrtf(bcx*bcx + bcy*bcy + bcz*bcz);
            float crx = bay*bcz - baz*bcy;
            float cry = baz*bcx - bax*bcz;
            float crz = bax*bcy - bay*bcx;
            float v1x = bay*crz - baz*cry;
            float v1y = baz*crx - bax*crz;
            float v1z = bax*cry - bay*crx;
            float n1 = fmaxf(sqrtf(v1x*v1x + v1y*v1y + v1z*v1z), 1e-12f);
            float v2x = -(bcy*crz - bcz*cry);
            float v2y = -(bcz*crx - bcx*crz);
            float v2z = -(bcx*cry - bcy*crx);
            float n2 = fmaxf(sqrtf(v2x*v2x + v2y*v2y + v2z*v2z), 1e-12f);
            float fax = af_*(v1x/n1)/ba_n, fay = af_*(v1y/n1)/ba_n, faz = af_*(v1z/n1)/ba_n;
            float fcx = af_*(v2x/n2)/bc_n, fcy = af_*(v2y/n2)/bc_n, fcz = af_*(v2z/n2)/bc_n;
            atomicAdd(&g_aacc[ai.u1*3+0], fax);
            atomicAdd(&g_aacc[ai.u1*3+1], fay);
            atomicAdd(&g_aacc[ai.u1*3+2], faz);
            atomicAdd(&g_aacc[ai.u2*3+0], -fax - fcx);
            atomicAdd(&g_aacc[ai.u2*3+1], -fay - fcy);
            atomicAdd(&g_aacc[ai.u2*3+2], -faz - fcz);
            atomicAdd(&g_aacc[ai.u3*3+0], fcx);
            atomicAdd(&g_aacc[ai.u3*3+1], fcy);
            atomicAdd(&g_aacc[ai.u3*3+2], fcz);
        }
    }
}

// ---------------------------------------------------------------------------
// integration tail
// ---------------------------------------------------------------------------
__global__ void finalize_kernel(const float* __restrict__ masses,
                                const float* __restrict__ dtp) {
    int i = blockIdx.x*blockDim.x + threadIdx.x;
    if (i >= NA) return;
    float m = masses[i], dt = dtp[0];
#pragma unroll
    for (int d = 0; d < 3; ++d) {
        float tf  = g_tf[i*3+d] / 100.0f;
        float acc = tf / m + g_aacc[i*3+d] / (m*100.0f);
        float al  = g_accs[i*3+d];
        g_vels[i*3+d] += 0.5f*(al + acc)*dt;
        g_accs[i*3+d]  = acc;
    }
}

__global__ void writeout_kernel(float* __restrict__ out) {
    int i = blockIdx.x*blockDim.x + threadIdx.x;
    if (i < NA*3) out[i] = g_coords[i];
}

// ---------------------------------------------------------------------------
// one-time precompute
// ---------------------------------------------------------------------------
__device__ void gemm128_dev(const float* __restrict__ A,
                            const float* __restrict__ W,
                            const float* __restrict__ bias,
                            float* __restrict__ C,
                            int M, int K, int fuse, int bm) {
    __shared__ float Ast[16][128];
    __shared__ float Ws [16][128];
    int tid = threadIdx.x;
    int tm = tid >> 4, tn = tid & 15;

    float acc[8][8];
#pragma unroll
    for (int i = 0; i < 8; ++i)
#pragma unroll
        for (int j = 0; j < 8; ++j) acc[i][j] = 0.0f;

    int arow = tid >> 1;
    int acol = (tid & 1) * 8;
    int wrow = tid >> 4;
    int wcol = (tid & 15) * 8;

    for (int kk = 0; kk < K; kk += 16) {
        {
            int grow = bm + arow;
            float4 v0 = make_float4(0,0,0,0), v1 = make_float4(0,0,0,0);
            if (grow < M && (kk + acol) < K) {
                const float* ap = A + (size_t)grow*K + kk + acol;
                v0 = *(const float4*)ap;
                v1 = *(const float4*)(ap + 4);
            }
            Ast[acol+0][arow] = v0.x; Ast[acol+1][arow] = v0.y;
            Ast[acol+2][arow] = v0.z; Ast[acol+3][arow] = v0.w;
            Ast[acol+4][arow] = v1.x; Ast[acol+5][arow] = v1.y;
            Ast[acol+6][arow] = v1.z; Ast[acol+7][arow] = v1.w;
        }
        {
            int gk = kk + wrow;
            float4 v0 = make_float4(0,0,0,0), v1 = make_float4(0,0,0,0);
            if (gk < K) {
                const float* wp = W + (size_t)gk*128 + wcol;
                v0 = *(const float4*)wp;
                v1 = *(const float4*)(wp + 4);
            }
            *(float4*)&Ws[wrow][wcol]   = v0;
            *(float4*)&Ws[wrow][wcol+4] = v1;
        }
        __syncthreads();
#pragma unroll
        for (int k2 = 0; k2 < 16; ++k2) {
            float4 a0 = *(const float4*)&Ast[k2][tm*8];
            float4 a1 = *(const float4*)&Ast[k2][tm*8+4];
            float4 w0 = *(const float4*)&Ws[k2][tn*8];
            float4 w1 = *(const float4*)&Ws[k2][tn*8+4];
            float av[8] = {a0.x,a0.y,a0.z,a0.w,a1.x,a1.y,a1.z,a1.w};
            float wv[8] = {w0.x,w0.y,w0.z,w0.w,w1.x,w1.y,w1.z,w1.w};
#pragma unroll
            for (int i = 0; i < 8; ++i)
#pragma unroll
                for (int j = 0; j < 8; ++j)
                    acc[i][j] += av[i]*wv[j];
        }
        __syncthreads();
    }
    float bv[8] = {0,0,0,0,0,0,0,0};
    if (fuse >= 1) {
        float4 b0 = *(const float4*)&bias[tn*8];
        float4 b1 = *(const float4*)&bias[tn*8+4];
        bv[0]=b0.x; bv[1]=b0.y; bv[2]=b0.z; bv[3]=b0.w;
        bv[4]=b1.x; bv[5]=b1.y; bv[6]=b1.z; bv[7]=b1.w;
    }
#pragma unroll
    for (int i = 0; i < 8; ++i) {
        int m = bm + tm*8 + i;
        if (m < M) {
            float o[8];
#pragma unroll
            for (int j = 0; j < 8; ++j) o[j] = acc[i][j] + bv[j];
            *(float4*)&C[(size_t)m*128 + tn*8]     = make_float4(o[0],o[1],o[2],o[3]);
            *(float4*)&C[(size_t)m*128 + tn*8 + 4] = make_float4(o[4],o[5],o[6],o[7]);
        }
    }
}

__global__ void precompute_kernel(const float* __restrict__ node_f,
                                  const float* __restrict__ dW1,
                                  const float* __restrict__ aW1,
                                  const float* __restrict__ ab1,
                                  const float* __restrict__ dW2,
                                  const float* __restrict__ dW3,
                                  const float* __restrict__ aW2) {
    int y = blockIdx.y;
    if (blockIdx.x == 63) {
        const float* src = (y == 0) ? dW2 : (y == 1) ? dW3 : aW2;
        __nv_bfloat16* dst = (y == 0) ? g_W2b : (y == 1) ? g_W3b : g_aW2b;
        for (int idx = threadIdx.x; idx < 128*128; idx += 256)
            dst[idx] = __float2bfloat16(src[idx]);
        return;
    }
    int bm = blockIdx.x * 128;
    if (y == 0)      gemm128_dev(node_f, dW1,          nullptr, g_P,  NA, 24, 0, bm);
    else if (y == 1) gemm128_dev(node_f, dW1 + 24*128, nullptr, g_Q,  NA, 24, 0, bm);
    else             gemm128_dev(node_f, aW1,          ab1,     g_A1, NA, 24, 1, bm);
}

// ---------------------------------------------------------------------------
// edge layer 1 (gather) -> bf16 row-major tiles
// ---------------------------------------------------------------------------
__global__ void edge_h1_kernel(const float* __restrict__ dW1,
                               const float* __restrict__ db1) {
    int widx = threadIdx.x >> 5, lane = threadIdx.x & 31;
    int e = blockIdx.x*8 + widx;
    if (e >= EPAD) return;
    __nv_bfloat16* dst = g_H1b + (size_t)e*128 + lane*4;

    if (e >= NE) { *(uint2*)dst = make_uint2(0u, 0u); return; }

    int i = e / KNN_K;
    int j = g_nbr[e];
    float4 pi = g_pos4[i];
    float4 pj = g_pos4[j];
    float dx = pi.x - pj.x;
    float dy = pi.y - pj.y;
    float dz = pi.z - pj.z;
    float dist = sqrtf(dx*dx + dy*dy + dz*dz);
    float inv = 1.0f / fmaxf(dist, 0.01f);
    if (lane == 0) {
        g_nd[e*3+0] = dx*inv; g_nd[e*3+1] = dy*inv; g_nd[e*3+2] = dz*inv;
    }
    float seq = fminf(fabsf((float)(i >> 2) - (float)(j >> 2)) / 5.0f, 1.0f);

    int n0 = lane*4;
    float4 pp  = *(const float4*)&g_P[i*128 + n0];
    float4 qq  = *(const float4*)&g_Q[j*128 + n0];
    float4 w48 = *(const float4*)&dW1[48*128 + n0];
    float4 w49 = *(const float4*)&dW1[49*128 + n0];
    float4 b   = *(const float4*)&db1[n0];
    float h0 = fast_tanh(pp.x + qq.x + dist*w48.x + seq*w49.x + b.x);
    float h1 = fast_tanh(pp.y + qq.y + dist*w48.y + seq*w49.y + b.y);
    float h2 = fast_tanh(pp.z + qq.z + dist*w48.z + seq*w49.z + b.z);
    float h3 = fast_tanh(pp.w + qq.w + dist*w48.w + seq*w49.w + b.w);
    __nv_bfloat162 p0 = __floats2bfloat162_rn(h0, h1);
    __nv_bfloat162 p1 = __floats2bfloat162_rn(h2, h3);
    uint2 v; v.x = *(u32*)&p0; v.y = *(u32*)&p1;
    *(uint2*)dst = v;
}

// ---------------------------------------------------------------------------
// fused dist MLP (wmma bf16)
// ---------------------------------------------------------------------------
#define SM_DIST (34816*3 + 10240 + 1536)
__global__ void __launch_bounds__(256, 2)
fused_dist_kernel(const float* __restrict__ db2, const float* __restrict__ db3,
                  const float* __restrict__ dW4, const float* __restrict__ db4) {
    extern __shared__ char sm[];
    __nv_bfloat16* sA  = (__nv_bfloat16*)sm;
    __nv_bfloat16* sW2 = (__nv_bfloat16*)(sm + 34816);
    __nv_bfloat16* sW3 = (__nv_bfloat16*)(sm + 69632);
    float*         ssc = (float*)(sm + 104448);
    float*         sb2 = (float*)(sm + 114688);
    float*         sb3 = sb2 + 128;
    float*         sw4 = sb3 + 128;
    int tid = threadIdx.x, w = tid >> 5, lane = tid & 31;

    {
        const uint4* gA  = (const uint4*)(g_H1b + (size_t)blockIdx.x*16384);
        const uint4* gW2 = (const uint4*)g_W2b;
        const uint4* gW3 = (const uint4*)g_W3b;
        for (int i = tid; i < 2048; i += 256) {
            int row = i >> 4, c8 = i & 15;
            int d = row*SP + c8*8;
            *(uint4*)&sA[d]  = gA[i];
            *(uint4*)&sW2[d] = gW2[i];
            *(uint4*)&sW3[d] = gW3[i];
        }
        if (tid < 128) { sb2[tid] = db2[tid]; sb3[tid] = db3[tid]; sw4[tid] = dW4[tid]; }
    }
    __syncthreads();

    float* sc = ssc + w*(16*SPF);
    int r = lane >> 1, ch = (lane & 1)*8;

    wmma::fragment<wmma::accumulator,16,16,16,float> acc[8];

#pragma unroll
    for (int f = 0; f < 8; ++f) wmma::fill_fragment(acc[f], 0.0f);
#pragma unroll
    for (int kt = 0; kt < 8; ++kt) {
        wmma::fragment<wmma::matrix_a,16,16,16,__nv_bfloat16,wmma::row_major> af;
        wmma::load_matrix_sync(af, &sA[(w*16)*SP + kt*16], SP);
#pragma unroll
        for (int f = 0; f < 8; ++f) {
            wmma::fragment<wmma::matrix_b,16,16,16,__nv_bfloat16,wmma::row_major> bf;
            wmma::load_matrix_sync(bf, &sW2[(kt*16)*SP + f*16], SP);
            wmma::mma_sync(acc[f], af, bf, acc[f]);
        }
    }
#pragma unroll
    for (int f = 0; f < 8; ++f) {
        wmma::store_matrix_sync(sc, acc[f], SPF, wmma::mem_row_major);
        __syncwarp();
        float v[8];
#pragma unroll
        for (int c = 0; c < 8; ++c)
            v[c] = fast_tanh(sc[r*SPF + ch + c] + sb2[f*16 + ch + c]);
        __nv_bfloat162 q0 = __floats2bfloat162_rn(v[0], v[1]);
        __nv_bfloat162 q1 = __floats2bfloat162_rn(v[2], v[3]);
        __nv_bfloat162 q2 = __floats2bfloat162_rn(v[4], v[5]);
        __nv_bfloat162 q3 = __floats2bfloat162_rn(v[6], v[7]);
        uint4 pk; pk.x = *(u32*)&q0; pk.y = *(u32*)&q1; pk.z = *(u32*)&q2; pk.w = *(u32*)&q3;
        *(uint4*)&sA[(w*16 + r)*SP + f*16 + ch] = pk;
        __syncwarp();
    }

#pragma unroll
    for (int f = 0; f < 8; ++f) wmma::fill_fragment(acc[f], 0.0f);
#pragma unroll
    for (int kt = 0; kt < 8; ++kt) {
        wmma::fragment<wmma::matrix_a,16,16,16,__nv_bfloat16,wmma::row_major> af;
        wmma::load_matrix_sync(af, &sA[(w*16)*SP + kt*16], SP);
#pragma unroll
        for (int f = 0; f < 8; ++f) {
            wmma::fragment<wmma::matrix_b,16,16,16,__nv_bfloat16,wmma::row_major> bf;
            wmma::load_matrix_sync(bf, &sW3[(kt*16)*SP + f*16], SP);
            wmma::mma_sync(acc[f], af, bf, acc[f]);
        }
    }
    float s = 0.0f;
#pragma unroll
    for (int f = 0; f < 8; ++f) {
        wmma::store_matrix_sync(sc, acc[f], SPF, wmma::mem_row_major);
        __syncwarp();
#pragma unroll
        for (int c = 0; c < 8; ++c) {
            int n = f*16 + ch + c;
            s += fast_tanh(sc[r*SPF + ch + c] + sb3[n]) * sw4[n];
        }
        __syncwarp();
    }
    s += __shfl_xor_sync(FULLM, s, 1);

    if ((lane & 1) == 0) {
        int e = blockIdx.x*128 + w*16 + r;
        if (e < NE) {
            s += db4[0];
            int a = e / KNN_K;
            atomicAdd(&g_tf[a*3+0], s * g_nd[e*3+0]);
            atomicAdd(&g_tf[a*3+1], s * g_nd[e*3+1]);
            atomicAdd(&g_tf[a*3+2], s * g_nd[e*3+2]);
        }
    }
}

// ---------------------------------------------------------------------------
// host launcher
// ---------------------------------------------------------------------------
extern "C" void kernel_launch(void* const* d_in, const int* in_sizes, int n_in,
                              void* d_out, int out_size) {
    const float* coords = (const float*)d_in[0];
    const float* node_f = (const float*)d_in[1];
    const float* masses = (const float*)d_in[3];
    const float* vels   = (const float*)d_in[4];
    const float* dW1 = (const float*)d_in[5];
    const float* db1 = (const float*)d_in[6];
    const float* dW2 = (const float*)d_in[7];
    const float* db2 = (const float*)d_in[8];
    const float* dW3 = (const float*)d_in[9];
    const float* db3 = (const float*)d_in[10];
    const float* dW4 = (const float*)d_in[11];
    const float* db4 = (const float*)d_in[12];
    const float* aW1 = (const float*)d_in[13];
    const float* ab1 = (const float*)d_in[14];
    const float* aW2 = (const float*)d_in[15];
    const float* ab2 = (const float*)d_in[16];
    const float* aW3 = (const float*)d_in[17];
    const float* ab3 = (const float*)d_in[18];
    const float* dtp  = (const float*)d_in[20];
    const float* temp = (const float*)d_in[21];
    float* out = (float*)d_out;

    cudaFuncSetAttribute(fused_dist_kernel, cudaFuncAttributeMaxDynamicSharedMemorySize, SM_DIST);
    cudaFuncSetAttribute(combo_kernel,      cudaFuncAttributeMaxDynamicSharedMemorySize, SM_COMBO);

    init_loss_kernel<<<95, 256>>>(coords, vels, temp, dtp, out + (out_size - 1));   // 0
    precompute_kernel<<<dim3(64,3), 256>>>(node_f, dW1, aW1, ab1, dW2, dW3, aW2);   // 1

    for (int s = 0; s < 3; ++s) {
        pos_build_kernel<<<32, 256>>>(dtp, s < 2 ? 1 : 0);                          // 2
        if (s == 2) break;

        combo_kernel<<<NTILE_A + 125, 256, SM_COMBO>>>(aW1, ab2, aW3, ab3);         // 3 <- ncu
        edge_h1_kernel<<<EPAD/8, 256>>>(dW1, db1);
        fused_dist_kernel<<<NTILE_E, 256, SM_DIST>>>(db2, db3, dW4, db4);
        finalize_kernel<<<32, 256>>>(masses, dtp);
    }

    writeout_kernel<<<94, 256>>>(out);
}

// round 16
// speedup vs baseline: 1.3495x; 1.2002x over previous
#include <cuda_runtime.h>
#include <cuda_bf16.h>
#include <mma.h>
#include <stdint.h>
#include <math.h>

using namespace nvcuda;

#define NA   8000
#define NRES 2000
#define KNN_K 15
#define NE   (NA*KNN_K)        // 120000
#define NANG 9998
#define EPAD (938*128)         // 120064 padded edge rows
#define NTILE_E 938
#define NTILE_A 79
#define SP  136                // smem bf16 row stride
#define SPF 20                 // float scratch row stride (combo/angle path)
#define SPD 16                 // float scratch row stride (dist path, 2 CTA/SM)

#define GDIM 16
#define NCELL (GDIM*GDIM*GDIM)   // 4096
#define GOX  (-48.0f)
#define GH   6.0f
#define GINV (1.0f/6.0f)
#define FULLM 0xffffffffu

typedef unsigned long long ull;
typedef unsigned int u32;

__device__ __forceinline__ float fast_tanh(float x) {
    float y; asm("tanh.approx.f32 %0, %1;" : "=f"(y) : "f"(x)); return y;
}

// ---------------------------------------------------------------------------
// scratch
// ---------------------------------------------------------------------------
__device__ float g_coords[NA*3];
__device__ float g_vels[NA*3];
__device__ float g_accs[NA*3];
__device__ float g_tf[NA*3];
__device__ float g_aacc[NA*3];
__device__ int   g_nbr[NE];
__device__ float g_nd[NE*3];
__device__ float g_P[8064*128];
__device__ float g_Q[8064*128];
__device__ float g_A1[8064*128];
__device__ float g_geom[NANG*8];
__device__ __align__(16) __nv_bfloat16 g_H1b[(size_t)NTILE_E*128*128];
__device__ __align__(16) __nv_bfloat16 g_W2b[128*128];
__device__ __align__(16) __nv_bfloat16 g_W3b[128*128];
__device__ __align__(16) __nv_bfloat16 g_aW2b[128*128];

// spatial grid (fixed bounds [-48,48]^3, 16^3 cells, h = 6.0 exact)
__device__ int  g_cellCount[NCELL];   // invariant: zero between builds
__device__ int  g_cellFill[NCELL];
__device__ int  g_cellStart[NCELL];
__device__ int  g_atomCell[NA];
__device__ int  g_done = 0;
__device__ __align__(16) float4 g_pos4[NA];
__device__ __align__(16) float4 g_spos4[NA];   // cell-sorted (x,y,z,id-bits)

__device__ __forceinline__ int cell_clamp(float v) {
    return min(GDIM-1, max(0, (int)((v - GOX) * GINV)));
}

// ---------------------------------------------------------------------------
// init + loss
// ---------------------------------------------------------------------------
__global__ void init_loss_kernel(const float* __restrict__ coords,
                                 const float* __restrict__ vels,
                                 const float* __restrict__ temp,
                                 const float* __restrict__ dtp,
                                 float* __restrict__ out_loss) {
    __shared__ float red[256];
    if (blockIdx.x < 94) {
        int i = blockIdx.x*256 + threadIdx.x;
        if (i < NA*3) {
            g_coords[i] = coords[i];
            g_vels[i]   = vels[i] * temp[0];
            g_accs[i]   = 0.0f;
        }
        return;
    }
    float T = temp[0], dt = dtp[0];
    float s = 0.0f;
    for (int i = threadIdx.x; i < NA*3; i += 256) {
        float c = coords[i];
        float x = ((vels[i]*T)*dt)*3.0f;
        float r = (c + x) - c;
        s += r*r;
    }
    red[threadIdx.x] = s; __syncthreads();
    for (int o = 128; o > 0; o >>= 1) {
        if (threadIdx.x < o) red[threadIdx.x] += red[threadIdx.x+o];
        __syncthreads();
    }
    if (threadIdx.x == 0) out_loss[0] = sqrtf(red[0] / (float)NA);
}

// ---------------------------------------------------------------------------
// pos update + full grid build
// ---------------------------------------------------------------------------
__global__ void pos_build_kernel(const float* __restrict__ dtp, int flag) {
    int t = threadIdx.x;
    int i = blockIdx.x*256 + t;                 // 32*256 = 8192
    float dt = dtp[0];
    if (i < NA) {
        float x = g_coords[3*i+0] + g_vels[3*i+0]*dt + 0.5f*g_accs[3*i+0]*dt*dt;
        float y = g_coords[3*i+1] + g_vels[3*i+1]*dt + 0.5f*g_accs[3*i+1]*dt*dt;
        float z = g_coords[3*i+2] + g_vels[3*i+2]*dt + 0.5f*g_accs[3*i+2]*dt*dt;
        g_coords[3*i+0] = x; g_coords[3*i+1] = y; g_coords[3*i+2] = z;
        g_pos4[i] = make_float4(x, y, z, 0.0f);
        g_aacc[3*i+0] = 0.f; g_aacc[3*i+1] = 0.f; g_aacc[3*i+2] = 0.f;
        g_tf[3*i+0] = 0.f;  g_tf[3*i+1] = 0.f;  g_tf[3*i+2] = 0.f;
        if (flag) {
            int c = (cell_clamp(z)*GDIM + cell_clamp(y))*GDIM + cell_clamp(x);
            g_atomCell[i] = c;
            atomicAdd(&g_cellCount[c], 1);
        }
    }
    if (!flag) return;

    __threadfence();
    __shared__ int last;
    if (t == 0) last = (atomicAdd(&g_done, 1) == (int)gridDim.x - 1);
    __syncthreads();
    if (!last) return;

    __shared__ int part[256];
    int base = t*16;
    int loc[16], s = 0;
#pragma unroll
    for (int k = 0; k < 16; ++k) { loc[k] = g_cellCount[base+k]; s += loc[k]; }
    part[t] = s; __syncthreads();
    for (int off = 1; off < 256; off <<= 1) {
        int v = (t >= off) ? part[t-off] : 0;
        __syncthreads();
        part[t] += v;
        __syncthreads();
    }
    int ex = part[t] - s;
#pragma unroll
    for (int k = 0; k < 16; ++k) { g_cellStart[base+k] = ex; ex += loc[k]; }
    __syncthreads();

    for (int a = t; a < NA; a += 256) {
        int c = g_atomCell[a];
        int p = g_cellStart[c] + atomicAdd(&g_cellFill[c], 1);
        float4 v = g_pos4[a];
        v.w = __int_as_float(a);
        g_spos4[p] = v;
    }
    __syncthreads();
#pragma unroll
    for (int k = 0; k < 16; ++k) { g_cellCount[base+k] = 0; g_cellFill[base+k] = 0; }
    if (t == 0) g_done = 0;
}

// ---------------------------------------------------------------------------
// angle indexing
// ---------------------------------------------------------------------------
struct AngleInfo { int u1, u2, u3, ct; };
__device__ __forceinline__ AngleInfo angle_info(int inst) {
    AngleInfo ai; int r;
    if (inst < 2000)      { r = inst;       ai.u1=4*r;   ai.u2=4*r+1; ai.u3=4*r+2; ai.ct=4*r+1; }
    else if (inst < 3999) { r = inst-2000;  ai.u1=4*r+1; ai.u2=4*r+2; ai.u3=4*r+4; ai.ct=4*r+2; }
    else if (inst < 5998) { r = inst-3999;  ai.u1=4*r+2; ai.u2=4*r+4; ai.u3=4*r+5; ai.ct=4*r+4; }
    else if (inst < 7998) { r = inst-5998;  ai.u1=4*r;   ai.u2=4*r+1; ai.u3=4*r+3; ai.ct=4*r+1; }
    else                  { r = inst-7998;  ai.u1=4*r+2; ai.u2=4*r+1; ai.u3=4*r+3; ai.ct=4*r+1; }
    return ai;
}

// ---------------------------------------------------------------------------
// COMBO: blocks [0, NTILE_A) = fused angle path; rest = KNN (4 lanes/query,
// sorted-insert selection; h=6 grid — empirically optimal).
// ---------------------------------------------------------------------------
#define SM_COMBO (34816*2 + 10240 + 1024)
__global__ void __launch_bounds__(256, 2)
combo_kernel(const float* __restrict__ aW1,
             const float* __restrict__ ab2, const float* __restrict__ aW3,
             const float* __restrict__ ab3) {
    extern __shared__ char sm[];
    int tid = threadIdx.x;

    if (blockIdx.x >= NTILE_A) {
        // ================= KNN path =================
        int kbid = blockIdx.x - NTILE_A;
        int p = (kbid*256 + tid) >> 2;
        int quarter = tid & 3;
        u32 grpmask = 0xFu << ((tid & 31) & ~3);

        float4 qp = g_spos4[p];
        int q = __float_as_int(qp.w);
        int cx = cell_clamp(qp.x), cy = cell_clamp(qp.y), cz = cell_clamp(qp.z);

        ull best[16];
#pragma unroll
        for (int k = 0; k < 16; ++k) best[k] = ~0ull;

        int segrot = 0;
        auto scan_run = [&](int c0, int c1) {
            int st = g_cellStart[c0];
            int en = (c1 == NCELL-1) ? NA : g_cellStart[c1+1];
            int b0 = st + ((quarter + segrot) & 3);
            ++segrot;
            for (int ii = b0; ii < en; ii += 4) {
                float4 pt = g_spos4[ii];
                float dx = qp.x - pt.x, dy = qp.y - pt.y, dz = qp.z - pt.z;
                float d2 = dx*dx + dy*dy + dz*dz;
                ull key = ((ull)__float_as_uint(d2) << 32) | (u32)__float_as_int(pt.w);
                if (key < best[15]) {
                    best[15] = key;
#pragma unroll
                    for (int tt = 15; tt > 0; --tt) {
                        ull a = best[tt-1], b = best[tt];
                        best[tt-1] = (a < b) ? a : b;
                        best[tt]   = (a < b) ? b : a;
                    }
                }
            }
        };

        for (int r = 0; r < GDIM; ++r) {
            int z0 = max(cz-r, 0), z1 = min(cz+r, GDIM-1);
            for (int zz = z0; zz <= z1; ++zz) {
                bool fz = (zz == cz-r) || (zz == cz+r);
                int y0 = max(cy-r, 0), y1 = min(cy+r, GDIM-1);
                for (int yy = y0; yy <= y1; ++yy) {
                    bool face = fz || (yy == cy-r) || (yy == cy+r);
                    int rb = (zz*GDIM + yy)*GDIM;
                    if (face) {
                        int x0 = max(cx-r, 0), x1 = min(cx+r, GDIM-1);
                        scan_run(rb + x0, rb + x1);
                    } else {
                        if (cx-r >= 0)      scan_run(rb + cx-r, rb + cx-r);
                        if (cx+r <= GDIM-1) scan_run(rb + cx+r, rb + cx+r);
                    }
                }
            }
            ull b3 = best[3], b15 = best[15];
#pragma unroll
            for (int o = 1; o <= 2; o <<= 1) {
                ull t3  = __shfl_xor_sync(grpmask, b3,  o);
                ull t15 = __shfl_xor_sync(grpmask, b15, o);
                b3  = (b3  > t3)  ? b3  : t3;
                b15 = (b15 < t15) ? b15 : t15;
            }
            ull ub = (b15 < b3) ? b15 : b3;
            if (ub != ~0ull) {
                float td2 = __uint_as_float((u32)(ub >> 32));
                float bnd = GH * (float)r;
                if (td2 <= bnd*bnd*0.9999f) break;
            }
        }

#pragma unroll
        for (int o = 1; o <= 2; o <<= 1) {
            ull other[16];
#pragma unroll
            for (int k = 0; k < 16; ++k)
                other[k] = __shfl_xor_sync(grpmask, best[k], o);
            ull c[16];
#pragma unroll
            for (int k = 0; k < 16; ++k) {
                ull a = best[k], b = other[15-k];
                c[k] = (a < b) ? a : b;
            }
#pragma unroll
            for (int j = 8; j > 0; j >>= 1) {
#pragma unroll
                for (int i2 = 0; i2 < 16; ++i2) {
                    if ((i2 & j) == 0) {
                        int pr = i2 | j;
                        ull lo = c[i2], hi = c[pr];
                        c[i2] = (lo < hi) ? lo : hi;
                        c[pr] = (lo < hi) ? hi : lo;
                    }
                }
            }
#pragma unroll
            for (int k = 0; k < 16; ++k) best[k] = c[k];
        }

        if (quarter == 0) {
#pragma unroll
            for (int k = 1; k < 16; ++k)
                g_nbr[q*KNN_K + k - 1] = (int)(u32)best[k];
        }
        return;
    }

    // ================= fused angle path =================
    __nv_bfloat16* sA = (__nv_bfloat16*)sm;
    __nv_bfloat16* sW = (__nv_bfloat16*)(sm + 34816);
    float*        ssc = (float*)(sm + 69632);
    float*       sab2 = (float*)(sm + 79872);
    float*       saw3 = sab2 + 128;
    int w = tid >> 5, lane = tid & 31;
    int n0 = lane*4;

    {
        const uint4* gW = (const uint4*)g_aW2b;
        for (int i = tid; i < 2048; i += 256) {
            int row = i >> 4, c8 = i & 15;
            *(uint4*)&sW[row*SP + c8*8] = gW[i];
        }
        if (tid < 128) { sab2[tid] = ab2[tid]; saw3[tid] = aW3[tid]; }
    }

    // geom + layer1 -> sA (one warp per row, 16 iterations)
    {
        float4 w24 = *(const float4*)&aW1[24*128 + n0];
        int i0 = blockIdx.x*128;
#pragma unroll 1
        for (int it = 0; it < 16; ++it) {
            int row = it*8 + w;
            int inst = i0 + row;
            uint2 v = make_uint2(0u, 0u);
            if (inst < NANG) {
                AngleInfo ai = angle_info(inst);
                float bax = g_coords[ai.u1*3+0] - g_coords[ai.u2*3+0];
                float bay = g_coords[ai.u1*3+1] - g_coords[ai.u2*3+1];
                float baz = g_coords[ai.u1*3+2] - g_coords[ai.u2*3+2];
                float bcx = g_coords[ai.u3*3+0] - g_coords[ai.u2*3+0];
                float bcy = g_coords[ai.u3*3+1] - g_coords[ai.u2*3+1];
                float bcz = g_coords[ai.u3*3+2] - g_coords[ai.u2*3+2];
                float ba_n = sqrtf(bax*bax + bay*bay + baz*baz);
                float bc_n = sqrtf(bcx*bcx + bcy*bcy + bcz*bcz);
                float cosang = (bax*bcx + bay*bcy + baz*bcz) / (ba_n * bc_n);
                cosang = fminf(fmaxf(cosang, -1.0f + 1e-6f), 1.0f - 1e-6f);
                float ang = acosf(cosang);
                if (lane == 0) {
                    g_geom[inst*8+0]=bax; g_geom[inst*8+1]=bay; g_geom[inst*8+2]=baz;
                    g_geom[inst*8+3]=bcx; g_geom[inst*8+4]=bcy; g_geom[inst*8+5]=bcz;
                }
                float4 a1 = *(const float4*)&g_A1[ai.ct*128 + n0];
                float h0 = fast_tanh(a1.x + ang*w24.x);
                float h1 = fast_tanh(a1.y + ang*w24.y);
                float h2 = fast_tanh(a1.z + ang*w24.z);
                float h3 = fast_tanh(a1.w + ang*w24.w);
                __nv_bfloat162 p0 = __floats2bfloat162_rn(h0, h1);
                __nv_bfloat162 p1 = __floats2bfloat162_rn(h2, h3);
                v.x = *(u32*)&p0; v.y = *(u32*)&p1;
            }
            *(uint2*)&sA[row*SP + n0] = v;
        }
    }
    __syncthreads();

    float* sc = ssc + w*(16*SPF);
    int r = lane >> 1, ch = (lane & 1)*8;

    wmma::fragment<wmma::accumulator,16,16,16,float> acc[8];
#pragma unroll
    for (int f = 0; f < 8; ++f) wmma::fill_fragment(acc[f], 0.0f);
#pragma unroll
    for (int kt = 0; kt < 8; ++kt) {
        wmma::fragment<wmma::matrix_a,16,16,16,__nv_bfloat16,wmma::row_major> af;
        wmma::load_matrix_sync(af, &sA[(w*16)*SP + kt*16], SP);
#pragma unroll
        for (int f = 0; f < 8; ++f) {
            wmma::fragment<wmma::matrix_b,16,16,16,__nv_bfloat16,wmma::row_major> bf;
            wmma::load_matrix_sync(bf, &sW[(kt*16)*SP + f*16], SP);
            wmma::mma_sync(acc[f], af, bf, acc[f]);
        }
    }

    float s = 0.0f;
#pragma unroll
    for (int f = 0; f < 8; ++f) {
        wmma::store_matrix_sync(sc, acc[f], SPF, wmma::mem_row_major);
        __syncwarp();
#pragma unroll
        for (int c = 0; c < 8; ++c) {
            int n = f*16 + ch + c;
            s += fast_tanh(sc[r*SPF + ch + c] + sab2[n]) * saw3[n];
        }
        __syncwarp();
    }
    s += __shfl_xor_sync(FULLM, s, 1);

    if ((lane & 1) == 0) {
        int inst = blockIdx.x*128 + w*16 + r;
        if (inst < NANG) {
            float af_ = s + ab3[0];
            AngleInfo ai = angle_info(inst);
            float bax=g_geom[inst*8+0], bay=g_geom[inst*8+1], baz=g_geom[inst*8+2];
            float bcx=g_geom[inst*8+3], bcy=g_geom[inst*8+4], bcz=g_geom[inst*8+5];
            float ba_n = sqrtf(bax*bax + bay*bay + baz*baz);
            float bc_n = sqrtf(bcx*bcx + bcy*bcy + bcz*bcz);
            float crx = bay*bcz - baz*bcy;
            float cry = baz*bcx - bax*bcz;
            float crz = bax*bcy - bay*bcx;
            float v1x = bay*crz - baz*cry;
            float v1y = baz*crx - bax*crz;
            float v1z = bax*cry - bay*crx;
            float n1 = fmaxf(sqrtf(v1x*v1x + v1y*v1y + v1z*v1z), 1e-12f);
            float v2x = -(bcy*crz - bcz*cry);
            float v2y = -(bcz*crx - bcx*crz);
            float v2z = -(bcx*cry - bcy*crx);
            float n2 = fmaxf(sqrtf(v2x*v2x + v2y*v2y + v2z*v2z), 1e-12f);
            float fax = af_*(v1x/n1)/ba_n, fay = af_*(v1y/n1)/ba_n, faz = af_*(v1z/n1)/ba_n;
            float fcx = af_*(v2x/n2)/bc_n, fcy = af_*(v2y/n2)/bc_n, fcz = af_*(v2z/n2)/bc_n;
            atomicAdd(&g_aacc[ai.u1*3+0], fax);
            atomicAdd(&g_aacc[ai.u1*3+1], fay);
            atomicAdd(&g_aacc[ai.u1*3+2], faz);
            atomicAdd(&g_aacc[ai.u2*3+0], -fax - fcx);
            atomicAdd(&g_aacc[ai.u2*3+1], -fay - fcy);
            atomicAdd(&g_aacc[ai.u2*3+2], -faz - fcz);
            atomicAdd(&g_aacc[ai.u3*3+0], fcx);
            atomicAdd(&g_aacc[ai.u3*3+1], fcy);
            atomicAdd(&g_aacc[ai.u3*3+2], fcz);
        }
    }
}

// ---------------------------------------------------------------------------
// integration tail
// ---------------------------------------------------------------------------
__global__ void finalize_kernel(const float* __restrict__ masses,
                                const float* __restrict__ dtp) {
    int i = blockIdx.x*blockDim.x + threadIdx.x;
    if (i >= NA) return;
    float m = masses[i], dt = dtp[0];
#pragma unroll
    for (int d = 0; d < 3; ++d) {
        float tf  = g_tf[i*3+d] / 100.0f;
        float acc = tf / m + g_aacc[i*3+d] / (m*100.0f);
        float al  = g_accs[i*3+d];
        g_vels[i*3+d] += 0.5f*(al + acc)*dt;
        g_accs[i*3+d]  = acc;
    }
}

__global__ void writeout_kernel(float* __restrict__ out) {
    int i = blockIdx.x*blockDim.x + threadIdx.x;
    if (i < NA*3) out[i] = g_coords[i];
}

// ---------------------------------------------------------------------------
// one-time precompute
// ---------------------------------------------------------------------------
__device__ void gemm128_dev(const float* __restrict__ A,
                            const float* __restrict__ W,
                            const float* __restrict__ bias,
                            float* __restrict__ C,
                            int M, int K, int fuse, int bm) {
    __shared__ float Ast[16][128];
    __shared__ float Ws [16][128];
    int tid = threadIdx.x;
    int tm = tid >> 4, tn = tid & 15;

    float acc[8][8];
#pragma unroll
    for (int i = 0; i < 8; ++i)
#pragma unroll
        for (int j = 0; j < 8; ++j) acc[i][j] = 0.0f;

    int arow = tid >> 1;
    int acol = (tid & 1) * 8;
    int wrow = tid >> 4;
    int wcol = (tid & 15) * 8;

    for (int kk = 0; kk < K; kk += 16) {
        {
            int grow = bm + arow;
            float4 v0 = make_float4(0,0,0,0), v1 = make_float4(0,0,0,0);
            if (grow < M && (kk + acol) < K) {
                const float* ap = A + (size_t)grow*K + kk + acol;
                v0 = *(const float4*)ap;
                v1 = *(const float4*)(ap + 4);
            }
            Ast[acol+0][arow] = v0.x; Ast[acol+1][arow] = v0.y;
            Ast[acol+2][arow] = v0.z; Ast[acol+3][arow] = v0.w;
            Ast[acol+4][arow] = v1.x; Ast[acol+5][arow] = v1.y;
            Ast[acol+6][arow] = v1.z; Ast[acol+7][arow] = v1.w;
        }
        {
            int gk = kk + wrow;
            float4 v0 = make_float4(0,0,0,0), v1 = make_float4(0,0,0,0);
            if (gk < K) {
                const float* wp = W + (size_t)gk*128 + wcol;
                v0 = *(const float4*)wp;
                v1 = *(const float4*)(wp + 4);
            }
            *(float4*)&Ws[wrow][wcol]   = v0;
            *(float4*)&Ws[wrow][wcol+4] = v1;
        }
        __syncthreads();
#pragma unroll
        for (int k2 = 0; k2 < 16; ++k2) {
            float4 a0 = *(const float4*)&Ast[k2][tm*8];
            float4 a1 = *(const float4*)&Ast[k2][tm*8+4];
            float4 w0 = *(const float4*)&Ws[k2][tn*8];
            float4 w1 = *(const float4*)&Ws[k2][tn*8+4];
            float av[8] = {a0.x,a0.y,a0.z,a0.w,a1.x,a1.y,a1.z,a1.w};
            float wv[8] = {w0.x,w0.y,w0.z,w0.w,w1.x,w1.y,w1.z,w1.w};
#pragma unroll
            for (int i = 0; i < 8; ++i)
#pragma unroll
                for (int j = 0; j < 8; ++j)
                    acc[i][j] += av[i]*wv[j];
        }
        __syncthreads();
    }
    float bv[8] = {0,0,0,0,0,0,0,0};
    if (fuse >= 1) {
        float4 b0 = *(const float4*)&bias[tn*8];
        float4 b1 = *(const float4*)&bias[tn*8+4];
        bv[0]=b0.x; bv[1]=b0.y; bv[2]=b0.z; bv[3]=b0.w;
        bv[4]=b1.x; bv[5]=b1.y; bv[6]=b1.z; bv[7]=b1.w;
    }
#pragma unroll
    for (int i = 0; i < 8; ++i) {
        int m = bm + tm*8 + i;
        if (m < M) {
            float o[8];
#pragma unroll
            for (int j = 0; j < 8; ++j) o[j] = acc[i][j] + bv[j];
            *(float4*)&C[(size_t)m*128 + tn*8]     = make_float4(o[0],o[1],o[2],o[3]);
            *(float4*)&C[(size_t)m*128 + tn*8 + 4] = make_float4(o[4],o[5],o[6],o[7]);
        }
    }
}

__global__ void precompute_kernel(const float* __restrict__ node_f,
                                  const float* __restrict__ dW1,
                                  const float* __restrict__ aW1,
                                  const float* __restrict__ ab1,
                                  const float* __restrict__ dW2,
                                  const float* __restrict__ dW3,
                                  const float* __restrict__ aW2) {
    int y = blockIdx.y;
    if (blockIdx.x == 63) {
        const float* src = (y == 0) ? dW2 : (y == 1) ? dW3 : aW2;
        __nv_bfloat16* dst = (y == 0) ? g_W2b : (y == 1) ? g_W3b : g_aW2b;
        for (int idx = threadIdx.x; idx < 128*128; idx += 256)
            dst[idx] = __float2bfloat16(src[idx]);
        return;
    }
    int bm = blockIdx.x * 128;
    if (y == 0)      gemm128_dev(node_f, dW1,          nullptr, g_P,  NA, 24, 0, bm);
    else if (y == 1) gemm128_dev(node_f, dW1 + 24*128, nullptr, g_Q,  NA, 24, 0, bm);
    else             gemm128_dev(node_f, aW1,          ab1,     g_A1, NA, 24, 1, bm);
}

// ---------------------------------------------------------------------------
// edge layer 1 (gather) -> bf16 row-major tiles
// ---------------------------------------------------------------------------
__global__ void edge_h1_kernel(const float* __restrict__ dW1,
                               const float* __restrict__ db1) {
    int widx = threadIdx.x >> 5, lane = threadIdx.x & 31;
    int e = blockIdx.x*8 + widx;
    if (e >= EPAD) return;
    __nv_bfloat16* dst = g_H1b + (size_t)e*128 + lane*4;

    if (e >= NE) { *(uint2*)dst = make_uint2(0u, 0u); return; }

    int i = e / KNN_K;
    int j = g_nbr[e];
    float4 pi = g_pos4[i];
    float4 pj = g_pos4[j];
    float dx = pi.x - pj.x;
    float dy = pi.y - pj.y;
    float dz = pi.z - pj.z;
    float dist = sqrtf(dx*dx + dy*dy + dz*dz);
    float inv = 1.0f / fmaxf(dist, 0.01f);
    if (lane == 0) {
        g_nd[e*3+0] = dx*inv; g_nd[e*3+1] = dy*inv; g_nd[e*3+2] = dz*inv;
    }
    float seq = fminf(fabsf((float)(i >> 2) - (float)(j >> 2)) / 5.0f, 1.0f);

    int n0 = lane*4;
    float4 pp  = *(const float4*)&g_P[i*128 + n0];
    float4 qq  = *(const float4*)&g_Q[j*128 + n0];
    float4 w48 = *(const float4*)&dW1[48*128 + n0];
    float4 w49 = *(const float4*)&dW1[49*128 + n0];
    float4 b   = *(const float4*)&db1[n0];
    float h0 = fast_tanh(pp.x + qq.x + dist*w48.x + seq*w49.x + b.x);
    float h1 = fast_tanh(pp.y + qq.y + dist*w48.y + seq*w49.y + b.y);
    float h2 = fast_tanh(pp.z + qq.z + dist*w48.z + seq*w49.z + b.z);
    float h3 = fast_tanh(pp.w + qq.w + dist*w48.w + seq*w49.w + b.w);
    __nv_bfloat162 p0 = __floats2bfloat162_rn(h0, h1);
    __nv_bfloat162 p1 = __floats2bfloat162_rn(h2, h3);
    uint2 v; v.x = *(u32*)&p0; v.y = *(u32*)&p1;
    *(uint2*)dst = v;
}

// ---------------------------------------------------------------------------
// fused dist MLP (wmma bf16) — scratch stride SPD=16 so 2 CTAs/SM fit
// ---------------------------------------------------------------------------
#define SM_DIST (34816*3 + 8192 + 1536)
__global__ void __launch_bounds__(256, 2)
fused_dist_kernel(const float* __restrict__ db2, const float* __restrict__ db3,
                  const float* __restrict__ dW4, const float* __restrict__ db4) {
    extern __shared__ char sm[];
    __nv_bfloat16* sA  = (__nv_bfloat16*)sm;
    __nv_bfloat16* sW2 = (__nv_bfloat16*)(sm + 34816);
    __nv_bfloat16* sW3 = (__nv_bfloat16*)(sm + 69632);
    float*         ssc = (float*)(sm + 104448);
    float*         sb2 = (float*)(sm + 112640);
    float*         sb3 = sb2 + 128;
    float*         sw4 = sb3 + 128;
    int tid = threadIdx.x, w = tid >> 5, lane = tid & 31;

    {
        const uint4* gA  = (const uint4*)(g_H1b + (size_t)blockIdx.x*16384);
        const uint4* gW2 = (const uint4*)g_W2b;
        const uint4* gW3 = (const uint4*)g_W3b;
        for (int i = tid; i < 2048; i += 256) {
            int row = i >> 4, c8 = i & 15;
            int d = row*SP + c8*8;
            *(uint4*)&sA[d]  = gA[i];
            *(uint4*)&sW2[d] = gW2[i];
            *(uint4*)&sW3[d] = gW3[i];
        }
        if (tid < 128) { sb2[tid] = db2[tid]; sb3[tid] = db3[tid]; sw4[tid] = dW4[tid]; }
    }
    __syncthreads();

    float* sc = ssc + w*(16*SPD);
    int r = lane >> 1, ch = (lane & 1)*8;

    wmma::fragment<wmma::accumulator,16,16,16,float> acc[8];

#pragma unroll
    for (int f = 0; f < 8; ++f) wmma::fill_fragment(acc[f], 0.0f);
#pragma unroll
    for (int kt = 0; kt < 8; ++kt) {
        wmma::fragment<wmma::matrix_a,16,16,16,__nv_bfloat16,wmma::row_major> af;
        wmma::load_matrix_sync(af, &sA[(w*16)*SP + kt*16], SP);
#pragma unroll
        for (int f = 0; f < 8; ++f) {
            wmma::fragment<wmma::matrix_b,16,16,16,__nv_bfloat16,wmma::row_major> bf;
            wmma::load_matrix_sync(bf, &sW2[(kt*16)*SP + f*16], SP);
            wmma::mma_sync(acc[f], af, bf, acc[f]);
        }
    }
#pragma unroll
    for (int f = 0; f < 8; ++f) {
        wmma::store_matrix_sync(sc, acc[f], SPD, wmma::mem_row_major);
        __syncwarp();
        float v[8];
#pragma unroll
        for (int c = 0; c < 8; ++c)
            v[c] = fast_tanh(sc[r*SPD + ch + c] + sb2[f*16 + ch + c]);
        __nv_bfloat162 q0 = __floats2bfloat162_rn(v[0], v[1]);
        __nv_bfloat162 q1 = __floats2bfloat162_rn(v[2], v[3]);
        __nv_bfloat162 q2 = __floats2bfloat162_rn(v[4], v[5]);
        __nv_bfloat162 q3 = __floats2bfloat162_rn(v[6], v[7]);
        uint4 pk; pk.x = *(u32*)&q0; pk.y = *(u32*)&q1; pk.z = *(u32*)&q2; pk.w = *(u32*)&q3;
        *(uint4*)&sA[(w*16 + r)*SP + f*16 + ch] = pk;
        __syncwarp();
    }

#pragma unroll
    for (int f = 0; f < 8; ++f) wmma::fill_fragment(acc[f], 0.0f);
#pragma unroll
    for (int kt = 0; kt < 8; ++kt) {
        wmma::fragment<wmma::matrix_a,16,16,16,__nv_bfloat16,wmma::row_major> af;
        wmma::load_matrix_sync(af, &sA[(w*16)*SP + kt*16], SP);
#pragma unroll
        for (int f = 0; f < 8; ++f) {
            wmma::fragment<wmma::matrix_b,16,16,16,__nv_bfloat16,wmma::row_major> bf;
            wmma::load_matrix_sync(bf, &sW3[(kt*16)*SP + f*16], SP);
            wmma::mma_sync(acc[f], af, bf, acc[f]);
        }
    }
    float s = 0.0f;
#pragma unroll
    for (int f = 0; f < 8; ++f) {
        wmma::store_matrix_sync(sc, acc[f], SPD, wmma::mem_row_major);
        __syncwarp();
#pragma unroll
        for (int c = 0; c < 8; ++c) {
            int n = f*16 + ch + c;
            s += fast_tanh(sc[r*SPD + ch + c] + sb3[n]) * sw4[n];
        }
        __syncwarp();
    }
    s += __shfl_xor_sync(FULLM, s, 1);

    if ((lane & 1) == 0) {
        int e = blockIdx.x*128 + w*16 + r;
        if (e < NE) {
            s += db4[0];
            int a = e / KNN_K;
            atomicAdd(&g_tf[a*3+0], s * g_nd[e*3+0]);
            atomicAdd(&g_tf[a*3+1], s * g_nd[e*3+1]);
            atomicAdd(&g_tf[a*3+2], s * g_nd[e*3+2]);
        }
    }
}

// ---------------------------------------------------------------------------
// host launcher
// ---------------------------------------------------------------------------
extern "C" void kernel_launch(void* const* d_in, const int* in_sizes, int n_in,
                              void* d_out, int out_size) {
    const float* coords = (const float*)d_in[0];
    const float* node_f = (const float*)d_in[1];
    const float* masses = (const float*)d_in[3];
    const float* vels   = (const float*)d_in[4];
    const float* dW1 = (const float*)d_in[5];
    const float* db1 = (const float*)d_in[6];
    const float* dW2 = (const float*)d_in[7];
    const float* db2 = (const float*)d_in[8];
    const float* dW3 = (const float*)d_in[9];
    const float* db3 = (const float*)d_in[10];
    const float* dW4 = (const float*)d_in[11];
    const float* db4 = (const float*)d_in[12];
    const float* aW1 = (const float*)d_in[13];
    const float* ab1 = (const float*)d_in[14];
    const float* aW2 = (const float*)d_in[15];
    const float* ab2 = (const float*)d_in[16];
    const float* aW3 = (const float*)d_in[17];
    const float* ab3 = (const float*)d_in[18];
    const float* dtp  = (const float*)d_in[20];
    const float* temp = (const float*)d_in[21];
    float* out = (float*)d_out;

    cudaFuncSetAttribute(fused_dist_kernel, cudaFuncAttributeMaxDynamicSharedMemorySize, SM_DIST);
    cudaFuncSetAttribute(combo_kernel,      cudaFuncAttributeMaxDynamicSharedMemorySize, SM_COMBO);

    init_loss_kernel<<<95, 256>>>(coords, vels, temp, dtp, out + (out_size - 1));   // 0
    precompute_kernel<<<dim3(64,3), 256>>>(node_f, dW1, aW1, ab1, dW2, dW3, aW2);   // 1

    for (int s = 0; s < 3; ++s) {
        pos_build_kernel<<<32, 256>>>(dtp, s < 2 ? 1 : 0);                          // 2
        if (s == 2) break;

        combo_kernel<<<NTILE_A + 125, 256, SM_COMBO>>>(aW1, ab2, aW3, ab3);         // 3 <- ncu
        edge_h1_kernel<<<EPAD/8, 256>>>(dW1, db1);
        fused_dist_kernel<<<NTILE_E, 256, SM_DIST>>>(db2, db3, dW4, db4);
        finalize_kernel<<<32, 256>>>(masses, dtp);
    }

    writeout_kernel<<<94, 256>>>(out);
}

// round 17
// speedup vs baseline: 1.4580x; 1.0804x over previous
#include <cuda_runtime.h>
#include <cuda_bf16.h>
#include <mma.h>
#include <stdint.h>
#include <math.h>

using namespace nvcuda;

#define NA   8000
#define NRES 2000
#define KNN_K 15
#define NE   (NA*KNN_K)        // 120000
#define NANG 9998
#define EPAD (938*128)         // 120064 padded edge rows
#define NTILE_E 938
#define NTILE_A 79
#define NKNNB 125
#define SP  136                // smem bf16 row stride
#define SPF 20                 // float scratch row stride (combo/angle path)
#define SPD 16                 // float scratch row stride (dist path, 2 CTA/SM)

#define GDIM 16
#define NCELL (GDIM*GDIM*GDIM)   // 4096
#define GOX  (-48.0f)
#define GH   6.0f
#define GINV (1.0f/6.0f)
#define FULLM 0xffffffffu

typedef unsigned long long ull;
typedef unsigned int u32;

__device__ __forceinline__ float fast_tanh(float x) {
    float y; asm("tanh.approx.f32 %0, %1;" : "=f"(y) : "f"(x)); return y;
}

// ---------------------------------------------------------------------------
// scratch
// ---------------------------------------------------------------------------
__device__ float g_coords[NA*3];
__device__ float g_vels[NA*3];
__device__ float g_accs[NA*3];
__device__ float g_tf[NA*3];
__device__ float g_aacc[NA*3];
__device__ int   g_nbr[NE];
__device__ float g_nd[NE*3];
__device__ float g_P[8064*128];
__device__ float g_Q[8064*128];
__device__ float g_A1[8064*128];
__device__ float g_geom[NANG*8];
__device__ __align__(16) __nv_bfloat16 g_H1b[(size_t)NTILE_E*128*128];
__device__ __align__(16) __nv_bfloat16 g_W2b[128*128];
__device__ __align__(16) __nv_bfloat16 g_W3b[128*128];
__device__ __align__(16) __nv_bfloat16 g_aW2b[128*128];

// spatial grid (fixed bounds [-48,48]^3, 16^3 cells, h = 6.0 exact)
__device__ int  g_cellCount[NCELL];   // invariant: zero between builds
__device__ int  g_cellFill[NCELL];
__device__ int  g_cellStart[NCELL];
__device__ int  g_atomCell[NA];
__device__ int  g_done = 0;
__device__ __align__(16) float4 g_pos4[NA];
__device__ __align__(16) float4 g_spos4[NA];   // cell-sorted (x,y,z,id-bits)

__device__ __forceinline__ int cell_clamp(float v) {
    return min(GDIM-1, max(0, (int)((v - GOX) * GINV)));
}

// ---------------------------------------------------------------------------
// init + loss
// ---------------------------------------------------------------------------
__global__ void init_loss_kernel(const float* __restrict__ coords,
                                 const float* __restrict__ vels,
                                 const float* __restrict__ temp,
                                 const float* __restrict__ dtp,
                                 float* __restrict__ out_loss) {
    __shared__ float red[256];
    if (blockIdx.x < 94) {
        int i = blockIdx.x*256 + threadIdx.x;
        if (i < NA*3) {
            g_coords[i] = coords[i];
            g_vels[i]   = vels[i] * temp[0];
            g_accs[i]   = 0.0f;
        }
        return;
    }
    float T = temp[0], dt = dtp[0];
    float s = 0.0f;
    for (int i = threadIdx.x; i < NA*3; i += 256) {
        float c = coords[i];
        float x = ((vels[i]*T)*dt)*3.0f;
        float r = (c + x) - c;
        s += r*r;
    }
    red[threadIdx.x] = s; __syncthreads();
    for (int o = 128; o > 0; o >>= 1) {
        if (threadIdx.x < o) red[threadIdx.x] += red[threadIdx.x+o];
        __syncthreads();
    }
    if (threadIdx.x == 0) out_loss[0] = sqrtf(red[0] / (float)NA);
}

// ---------------------------------------------------------------------------
// pos update + full grid build
// ---------------------------------------------------------------------------
__global__ void pos_build_kernel(const float* __restrict__ dtp, int flag) {
    int t = threadIdx.x;
    int i = blockIdx.x*256 + t;                 // 32*256 = 8192
    float dt = dtp[0];
    if (i < NA) {
        float x = g_coords[3*i+0] + g_vels[3*i+0]*dt + 0.5f*g_accs[3*i+0]*dt*dt;
        float y = g_coords[3*i+1] + g_vels[3*i+1]*dt + 0.5f*g_accs[3*i+1]*dt*dt;
        float z = g_coords[3*i+2] + g_vels[3*i+2]*dt + 0.5f*g_accs[3*i+2]*dt*dt;
        g_coords[3*i+0] = x; g_coords[3*i+1] = y; g_coords[3*i+2] = z;
        g_pos4[i] = make_float4(x, y, z, 0.0f);
        g_aacc[3*i+0] = 0.f; g_aacc[3*i+1] = 0.f; g_aacc[3*i+2] = 0.f;
        g_tf[3*i+0] = 0.f;  g_tf[3*i+1] = 0.f;  g_tf[3*i+2] = 0.f;
        if (flag) {
            int c = (cell_clamp(z)*GDIM + cell_clamp(y))*GDIM + cell_clamp(x);
            g_atomCell[i] = c;
            atomicAdd(&g_cellCount[c], 1);
        }
    }
    if (!flag) return;

    __threadfence();
    __shared__ int last;
    if (t == 0) last = (atomicAdd(&g_done, 1) == (int)gridDim.x - 1);
    __syncthreads();
    if (!last) return;

    __shared__ int part[256];
    int base = t*16;
    int loc[16], s = 0;
#pragma unroll
    for (int k = 0; k < 16; ++k) { loc[k] = g_cellCount[base+k]; s += loc[k]; }
    part[t] = s; __syncthreads();
    for (int off = 1; off < 256; off <<= 1) {
        int v = (t >= off) ? part[t-off] : 0;
        __syncthreads();
        part[t] += v;
        __syncthreads();
    }
    int ex = part[t] - s;
#pragma unroll
    for (int k = 0; k < 16; ++k) { g_cellStart[base+k] = ex; ex += loc[k]; }
    __syncthreads();

    for (int a = t; a < NA; a += 256) {
        int c = g_atomCell[a];
        int p = g_cellStart[c] + atomicAdd(&g_cellFill[c], 1);
        float4 v = g_pos4[a];
        v.w = __int_as_float(a);
        g_spos4[p] = v;
    }
    __syncthreads();
#pragma unroll
    for (int k = 0; k < 16; ++k) { g_cellCount[base+k] = 0; g_cellFill[base+k] = 0; }
    if (t == 0) g_done = 0;
}

// ---------------------------------------------------------------------------
// angle indexing
// ---------------------------------------------------------------------------
struct AngleInfo { int u1, u2, u3, ct; };
__device__ __forceinline__ AngleInfo angle_info(int inst) {
    AngleInfo ai; int r;
    if (inst < 2000)      { r = inst;       ai.u1=4*r;   ai.u2=4*r+1; ai.u3=4*r+2; ai.ct=4*r+1; }
    else if (inst < 3999) { r = inst-2000;  ai.u1=4*r+1; ai.u2=4*r+2; ai.u3=4*r+4; ai.ct=4*r+2; }
    else if (inst < 5998) { r = inst-3999;  ai.u1=4*r+2; ai.u2=4*r+4; ai.u3=4*r+5; ai.ct=4*r+4; }
    else if (inst < 7998) { r = inst-5998;  ai.u1=4*r;   ai.u2=4*r+1; ai.u3=4*r+3; ai.ct=4*r+1; }
    else                  { r = inst-7998;  ai.u1=4*r+2; ai.u2=4*r+1; ai.u3=4*r+3; ai.ct=4*r+1; }
    return ai;
}

// ---------------------------------------------------------------------------
// COMBO: blocks [0, NKNNB) = KNN (LONG blocks launched first so they seat in
// wave 1); blocks [NKNNB, NKNNB+NTILE_A) = fused angle path (short, backfill).
// ---------------------------------------------------------------------------
#define SM_COMBO (34816*2 + 10240 + 1024)
__global__ void __launch_bounds__(256, 2)
combo_kernel(const float* __restrict__ aW1,
             const float* __restrict__ ab2, const float* __restrict__ aW3,
             const float* __restrict__ ab3) {
    extern __shared__ char sm[];
    int tid = threadIdx.x;

    if (blockIdx.x < NKNNB) {
        // ================= KNN path =================
        int kbid = blockIdx.x;
        int p = (kbid*256 + tid) >> 2;
        int quarter = tid & 3;
        u32 grpmask = 0xFu << ((tid & 31) & ~3);

        float4 qp = g_spos4[p];
        int q = __float_as_int(qp.w);
        int cx = cell_clamp(qp.x), cy = cell_clamp(qp.y), cz = cell_clamp(qp.z);

        ull best[16];
#pragma unroll
        for (int k = 0; k < 16; ++k) best[k] = ~0ull;

        int segrot = 0;
        auto scan_run = [&](int c0, int c1) {
            int st = g_cellStart[c0];
            int en = (c1 == NCELL-1) ? NA : g_cellStart[c1+1];
            int b0 = st + ((quarter + segrot) & 3);
            ++segrot;
            for (int ii = b0; ii < en; ii += 4) {
                float4 pt = g_spos4[ii];
                float dx = qp.x - pt.x, dy = qp.y - pt.y, dz = qp.z - pt.z;
                float d2 = dx*dx + dy*dy + dz*dz;
                ull key = ((ull)__float_as_uint(d2) << 32) | (u32)__float_as_int(pt.w);
                if (key < best[15]) {
                    best[15] = key;
#pragma unroll
                    for (int tt = 15; tt > 0; --tt) {
                        ull a = best[tt-1], b = best[tt];
                        best[tt-1] = (a < b) ? a : b;
                        best[tt]   = (a < b) ? b : a;
                    }
                }
            }
        };

        for (int r = 0; r < GDIM; ++r) {
            int z0 = max(cz-r, 0), z1 = min(cz+r, GDIM-1);
            for (int zz = z0; zz <= z1; ++zz) {
                bool fz = (zz == cz-r) || (zz == cz+r);
                int y0 = max(cy-r, 0), y1 = min(cy+r, GDIM-1);
                for (int yy = y0; yy <= y1; ++yy) {
                    bool face = fz || (yy == cy-r) || (yy == cy+r);
                    int rb = (zz*GDIM + yy)*GDIM;
                    if (face) {
                        int x0 = max(cx-r, 0), x1 = min(cx+r, GDIM-1);
                        scan_run(rb + x0, rb + x1);
                    } else {
                        if (cx-r >= 0)      scan_run(rb + cx-r, rb + cx-r);
                        if (cx+r <= GDIM-1) scan_run(rb + cx+r, rb + cx+r);
                    }
                }
            }
            ull b3 = best[3], b15 = best[15];
#pragma unroll
            for (int o = 1; o <= 2; o <<= 1) {
                ull t3  = __shfl_xor_sync(grpmask, b3,  o);
                ull t15 = __shfl_xor_sync(grpmask, b15, o);
                b3  = (b3  > t3)  ? b3  : t3;
                b15 = (b15 < t15) ? b15 : t15;
            }
            ull ub = (b15 < b3) ? b15 : b3;
            if (ub != ~0ull) {
                float td2 = __uint_as_float((u32)(ub >> 32));
                float bnd = GH * (float)r;
                if (td2 <= bnd*bnd*0.9999f) break;
            }
        }

#pragma unroll
        for (int o = 1; o <= 2; o <<= 1) {
            ull other[16];
#pragma unroll
            for (int k = 0; k < 16; ++k)
                other[k] = __shfl_xor_sync(grpmask, best[k], o);
            ull c[16];
#pragma unroll
            for (int k = 0; k < 16; ++k) {
                ull a = best[k], b = other[15-k];
                c[k] = (a < b) ? a : b;
            }
#pragma unroll
            for (int j = 8; j > 0; j >>= 1) {
#pragma unroll
                for (int i2 = 0; i2 < 16; ++i2) {
                    if ((i2 & j) == 0) {
                        int pr = i2 | j;
                        ull lo = c[i2], hi = c[pr];
                        c[i2] = (lo < hi) ? lo : hi;
                        c[pr] = (lo < hi) ? hi : lo;
                    }
                }
            }
#pragma unroll
            for (int k = 0; k < 16; ++k) best[k] = c[k];
        }

        if (quarter == 0) {
#pragma unroll
            for (int k = 1; k < 16; ++k)
                g_nbr[q*KNN_K + k - 1] = (int)(u32)best[k];
        }
        return;
    }

    // ================= fused angle path =================
    int abid = blockIdx.x - NKNNB;
    __nv_bfloat16* sA = (__nv_bfloat16*)sm;
    __nv_bfloat16* sW = (__nv_bfloat16*)(sm + 34816);
    float*        ssc = (float*)(sm + 69632);
    float*       sab2 = (float*)(sm + 79872);
    float*       saw3 = sab2 + 128;
    int w = tid >> 5, lane = tid & 31;
    int n0 = lane*4;

    {
        const uint4* gW = (const uint4*)g_aW2b;
        for (int i = tid; i < 2048; i += 256) {
            int row = i >> 4, c8 = i & 15;
            *(uint4*)&sW[row*SP + c8*8] = gW[i];
        }
        if (tid < 128) { sab2[tid] = ab2[tid]; saw3[tid] = aW3[tid]; }
    }

    // geom + layer1 -> sA (one warp per row, 16 iterations)
    {
        float4 w24 = *(const float4*)&aW1[24*128 + n0];
        int i0 = abid*128;
#pragma unroll 1
        for (int it = 0; it < 16; ++it) {
            int row = it*8 + w;
            int inst = i0 + row;
            uint2 v = make_uint2(0u, 0u);
            if (inst < NANG) {
                AngleInfo ai = angle_info(inst);
                float bax = g_coords[ai.u1*3+0] - g_coords[ai.u2*3+0];
                float bay = g_coords[ai.u1*3+1] - g_coords[ai.u2*3+1];
                float baz = g_coords[ai.u1*3+2] - g_coords[ai.u2*3+2];
                float bcx = g_coords[ai.u3*3+0] - g_coords[ai.u2*3+0];
                float bcy = g_coords[ai.u3*3+1] - g_coords[ai.u2*3+1];
                float bcz = g_coords[ai.u3*3+2] - g_coords[ai.u2*3+2];
                float ba_n = sqrtf(bax*bax + bay*bay + baz*baz);
                float bc_n = sqrtf(bcx*bcx + bcy*bcy + bcz*bcz);
                float cosang = (bax*bcx + bay*bcy + baz*bcz) / (ba_n * bc_n);
                cosang = fminf(fmaxf(cosang, -1.0f + 1e-6f), 1.0f - 1e-6f);
                float ang = acosf(cosang);
                if (lane == 0) {
                    g_geom[inst*8+0]=bax; g_geom[inst*8+1]=bay; g_geom[inst*8+2]=baz;
                    g_geom[inst*8+3]=bcx; g_geom[inst*8+4]=bcy; g_geom[inst*8+5]=bcz;
                }
                float4 a1 = *(const float4*)&g_A1[ai.ct*128 + n0];
                float h0 = fast_tanh(a1.x + ang*w24.x);
                float h1 = fast_tanh(a1.y + ang*w24.y);
                float h2 = fast_tanh(a1.z + ang*w24.z);
                float h3 = fast_tanh(a1.w + ang*w24.w);
                __nv_bfloat162 p0 = __floats2bfloat162_rn(h0, h1);
                __nv_bfloat162 p1 = __floats2bfloat162_rn(h2, h3);
                v.x = *(u32*)&p0; v.y = *(u32*)&p1;
            }
            *(uint2*)&sA[row*SP + n0] = v;
        }
    }
    __syncthreads();

    float* sc = ssc + w*(16*SPF);
    int r = lane >> 1, ch = (lane & 1)*8;

    wmma::fragment<wmma::accumulator,16,16,16,float> acc[8];
#pragma unroll
    for (int f = 0; f < 8; ++f) wmma::fill_fragment(acc[f], 0.0f);
#pragma unroll
    for (int kt = 0; kt < 8; ++kt) {
        wmma::fragment<wmma::matrix_a,16,16,16,__nv_bfloat16,wmma::row_major> af;
        wmma::load_matrix_sync(af, &sA[(w*16)*SP + kt*16], SP);
#pragma unroll
        for (int f = 0; f < 8; ++f) {
            wmma::fragment<wmma::matrix_b,16,16,16,__nv_bfloat16,wmma::row_major> bf;
            wmma::load_matrix_sync(bf, &sW[(kt*16)*SP + f*16], SP);
            wmma::mma_sync(acc[f], af, bf, acc[f]);
        }
    }

    float s = 0.0f;
#pragma unroll
    for (int f = 0; f < 8; ++f) {
        wmma::store_matrix_sync(sc, acc[f], SPF, wmma::mem_row_major);
        __syncwarp();
#pragma unroll
        for (int c = 0; c < 8; ++c) {
            int n = f*16 + ch + c;
            s += fast_tanh(sc[r*SPF + ch + c] + sab2[n]) * saw3[n];
        }
        __syncwarp();
    }
    s += __shfl_xor_sync(FULLM, s, 1);

    if ((lane & 1) == 0) {
        int inst = abid*128 + w*16 + r;
        if (inst < NANG) {
            float af_ = s + ab3[0];
            AngleInfo ai = angle_info(inst);
            float bax=g_geom[inst*8+0], bay=g_geom[inst*8+1], baz=g_geom[inst*8+2];
            float bcx=g_geom[inst*8+3], bcy=g_geom[inst*8+4], bcz=g_geom[inst*8+5];
            float ba_n = sqrtf(bax*bax + bay*bay + baz*baz);
            float bc_n = sqrtf(bcx*bcx + bcy*bcy + bcz*bcz);
            float crx = bay*bcz - baz*bcy;
            float cry = baz*bcx - bax*bcz;
            float crz = bax*bcy - bay*bcx;
            float v1x = bay*crz - baz*cry;
            float v1y = baz*crx - bax*crz;
            float v1z = bax*cry - bay*crx;
            float n1 = fmaxf(sqrtf(v1x*v1x + v1y*v1y + v1z*v1z), 1e-12f);
            float v2x = -(bcy*crz - bcz*cry);
            float v2y = -(bcz*crx - bcx*crz);
            float v2z = -(bcx*cry - bcy*crx);
            float n2 = fmaxf(sqrtf(v2x*v2x + v2y*v2y + v2z*v2z), 1e-12f);
            float fax = af_*(v1x/n1)/ba_n, fay = af_*(v1y/n1)/ba_n, faz = af_*(v1z/n1)/ba_n;
            float fcx = af_*(v2x/n2)/bc_n, fcy = af_*(v2y/n2)/bc_n, fcz = af_*(v2z/n2)/bc_n;
            atomicAdd(&g_aacc[ai.u1*3+0], fax);
            atomicAdd(&g_aacc[ai.u1*3+1], fay);
            atomicAdd(&g_aacc[ai.u1*3+2], faz);
            atomicAdd(&g_aacc[ai.u2*3+0], -fax - fcx);
            atomicAdd(&g_aacc[ai.u2*3+1], -fay - fcy);
            atomicAdd(&g_aacc[ai.u2*3+2], -faz - fcz);
            atomicAdd(&g_aacc[ai.u3*3+0], fcx);
            atomicAdd(&g_aacc[ai.u3*3+1], fcy);
            atomicAdd(&g_aacc[ai.u3*3+2], fcz);
        }
    }
}

// ---------------------------------------------------------------------------
// integration tail
// ---------------------------------------------------------------------------
__global__ void finalize_kernel(const float* __restrict__ masses,
                                const float* __restrict__ dtp) {
    int i = blockIdx.x*blockDim.x + threadIdx.x;
    if (i >= NA) return;
    float m = masses[i], dt = dtp[0];
#pragma unroll
    for (int d = 0; d < 3; ++d) {
        float tf  = g_tf[i*3+d] / 100.0f;
        float acc = tf / m + g_aacc[i*3+d] / (m*100.0f);
        float al  = g_accs[i*3+d];
        g_vels[i*3+d] += 0.5f*(al + acc)*dt;
        g_accs[i*3+d]  = acc;
    }
}

__global__ void writeout_kernel(float* __restrict__ out) {
    int i = blockIdx.x*blockDim.x + threadIdx.x;
    if (i < NA*3) out[i] = g_coords[i];
}

// ---------------------------------------------------------------------------
// one-time precompute
// ---------------------------------------------------------------------------
__device__ void gemm128_dev(const float* __restrict__ A,
                            const float* __restrict__ W,
                            const float* __restrict__ bias,
                            float* __restrict__ C,
                            int M, int K, int fuse, int bm) {
    __shared__ float Ast[16][128];
    __shared__ float Ws [16][128];
    int tid = threadIdx.x;
    int tm = tid >> 4, tn = tid & 15;

    float acc[8][8];
#pragma unroll
    for (int i = 0; i < 8; ++i)
#pragma unroll
        for (int j = 0; j < 8; ++j) acc[i][j] = 0.0f;

    int arow = tid >> 1;
    int acol = (tid & 1) * 8;
    int wrow = tid >> 4;
    int wcol = (tid & 15) * 8;

    for (int kk = 0; kk < K; kk += 16) {
        {
            int grow = bm + arow;
            float4 v0 = make_float4(0,0,0,0), v1 = make_float4(0,0,0,0);
            if (grow < M && (kk + acol) < K) {
                const float* ap = A + (size_t)grow*K + kk + acol;
                v0 = *(const float4*)ap;
                v1 = *(const float4*)(ap + 4);
            }
            Ast[acol+0][arow] = v0.x; Ast[acol+1][arow] = v0.y;
            Ast[acol+2][arow] = v0.z; Ast[acol+3][arow] = v0.w;
            Ast[acol+4][arow] = v1.x; Ast[acol+5][arow] = v1.y;
            Ast[acol+6][arow] = v1.z; Ast[acol+7][arow] = v1.w;
        }
        {
            int gk = kk + wrow;
            float4 v0 = make_float4(0,0,0,0), v1 = make_float4(0,0,0,0);
            if (gk < K) {
                const float* wp = W + (size_t)gk*128 + wcol;
                v0 = *(const float4*)wp;
                v1 = *(const float4*)(wp + 4);
            }
            *(float4*)&Ws[wrow][wcol]   = v0;
            *(float4*)&Ws[wrow][wcol+4] = v1;
        }
        __syncthreads();
#pragma unroll
        for (int k2 = 0; k2 < 16; ++k2) {
            float4 a0 = *(const float4*)&Ast[k2][tm*8];
            float4 a1 = *(const float4*)&Ast[k2][tm*8+4];
            float4 w0 = *(const float4*)&Ws[k2][tn*8];
            float4 w1 = *(const float4*)&Ws[k2][tn*8+4];
            float av[8] = {a0.x,a0.y,a0.z,a0.w,a1.x,a1.y,a1.z,a1.w};
            float wv[8] = {w0.x,w0.y,w0.z,w0.w,w1.x,w1.y,w1.z,w1.w};
#pragma unroll
            for (int i = 0; i < 8; ++i)
#pragma unroll
                for (int j = 0; j < 8; ++j)
                    acc[i][j] += av[i]*wv[j];
        }
        __syncthreads();
    }
    float bv[8] = {0,0,0,0,0,0,0,0};
    if (fuse >= 1) {
        float4 b0 = *(const float4*)&bias[tn*8];
        float4 b1 = *(const float4*)&bias[tn*8+4];
        bv[0]=b0.x; bv[1]=b0.y; bv[2]=b0.z; bv[3]=b0.w;
        bv[4]=b1.x; bv[5]=b1.y; bv[6]=b1.z; bv[7]=b1.w;
    }
#pragma unroll
    for (int i = 0; i < 8; ++i) {
        int m = bm + tm*8 + i;
        if (m < M) {
            float o[8];
#pragma unroll
            for (int j = 0; j < 8; ++j) o[j] = acc[i][j] + bv[j];
            *(float4*)&C[(size_t)m*128 + tn*8]     = make_float4(o[0],o[1],o[2],o[3]);
            *(float4*)&C[(size_t)m*128 + tn*8 + 4] = make_float4(o[4],o[5],o[6],o[7]);
        }
    }
}

__global__ void precompute_kernel(const float* __restrict__ node_f,
                                  const float* __restrict__ dW1,
                                  const float* __restrict__ aW1,
                                  const float* __restrict__ ab1,
                                  const float* __restrict__ dW2,
                                  const float* __restrict__ dW3,
                                  const float* __restrict__ aW2) {
    int y = blockIdx.y;
    if (blockIdx.x == 63) {
        const float* src = (y == 0) ? dW2 : (y == 1) ? dW3 : aW2;
        __nv_bfloat16* dst = (y == 0) ? g_W2b : (y == 1) ? g_W3b : g_aW2b;
        for (int idx = threadIdx.x; idx < 128*128; idx += 256)
            dst[idx] = __float2bfloat16(src[idx]);
        return;
    }
    int bm = blockIdx.x * 128;
    if (y == 0)      gemm128_dev(node_f, dW1,          nullptr, g_P,  NA, 24, 0, bm);
    else if (y == 1) gemm128_dev(node_f, dW1 + 24*128, nullptr, g_Q,  NA, 24, 0, bm);
    else             gemm128_dev(node_f, aW1,          ab1,     g_A1, NA, 24, 1, bm);
}

// ---------------------------------------------------------------------------
// edge layer 1 (gather) -> bf16 row-major tiles
// ---------------------------------------------------------------------------
__global__ void edge_h1_kernel(const float* __restrict__ dW1,
                               const float* __restrict__ db1) {
    int widx = threadIdx.x >> 5, lane = threadIdx.x & 31;
    int e = blockIdx.x*8 + widx;
    if (e >= EPAD) return;
    __nv_bfloat16* dst = g_H1b + (size_t)e*128 + lane*4;

    if (e >= NE) { *(uint2*)dst = make_uint2(0u, 0u); return; }

    int i = e / KNN_K;
    int j = g_nbr[e];
    float4 pi = g_pos4[i];
    float4 pj = g_pos4[j];
    float dx = pi.x - pj.x;
    float dy = pi.y - pj.y;
    float dz = pi.z - pj.z;
    float dist = sqrtf(dx*dx + dy*dy + dz*dz);
    float inv = 1.0f / fmaxf(dist, 0.01f);
    if (lane == 0) {
        g_nd[e*3+0] = dx*inv; g_nd[e*3+1] = dy*inv; g_nd[e*3+2] = dz*inv;
    }
    float seq = fminf(fabsf((float)(i >> 2) - (float)(j >> 2)) / 5.0f, 1.0f);

    int n0 = lane*4;
    float4 pp  = *(const float4*)&g_P[i*128 + n0];
    float4 qq  = *(const float4*)&g_Q[j*128 + n0];
    float4 w48 = *(const float4*)&dW1[48*128 + n0];
    float4 w49 = *(const float4*)&dW1[49*128 + n0];
    float4 b   = *(const float4*)&db1[n0];
    float h0 = fast_tanh(pp.x + qq.x + dist*w48.x + seq*w49.x + b.x);
    float h1 = fast_tanh(pp.y + qq.y + dist*w48.y + seq*w49.y + b.y);
    float h2 = fast_tanh(pp.z + qq.z + dist*w48.z + seq*w49.z + b.z);
    float h3 = fast_tanh(pp.w + qq.w + dist*w48.w + seq*w49.w + b.w);
    __nv_bfloat162 p0 = __floats2bfloat162_rn(h0, h1);
    __nv_bfloat162 p1 = __floats2bfloat162_rn(h2, h3);
    uint2 v; v.x = *(u32*)&p0; v.y = *(u32*)&p1;
    *(uint2*)dst = v;
}

// ---------------------------------------------------------------------------
// fused dist MLP (wmma bf16) — scratch stride SPD=16 so 2 CTAs/SM fit
// ---------------------------------------------------------------------------
#define SM_DIST (34816*3 + 8192 + 1536)
__global__ void __launch_bounds__(256, 2)
fused_dist_kernel(const float* __restrict__ db2, const float* __restrict__ db3,
                  const float* __restrict__ dW4, const float* __restrict__ db4) {
    extern __shared__ char sm[];
    __nv_bfloat16* sA  = (__nv_bfloat16*)sm;
    __nv_bfloat16* sW2 = (__nv_bfloat16*)(sm + 34816);
    __nv_bfloat16* sW3 = (__nv_bfloat16*)(sm + 69632);
    float*         ssc = (float*)(sm + 104448);
    float*         sb2 = (float*)(sm + 112640);
    float*         sb3 = sb2 + 128;
    float*         sw4 = sb3 + 128;
    int tid = threadIdx.x, w = tid >> 5, lane = tid & 31;

    {
        const uint4* gA  = (const uint4*)(g_H1b + (size_t)blockIdx.x*16384);
        const uint4* gW2 = (const uint4*)g_W2b;
        const uint4* gW3 = (const uint4*)g_W3b;
        for (int i = tid; i < 2048; i += 256) {
            int row = i >> 4, c8 = i & 15;
            int d = row*SP + c8*8;
            *(uint4*)&sA[d]  = gA[i];
            *(uint4*)&sW2[d] = gW2[i];
            *(uint4*)&sW3[d] = gW3[i];
        }
        if (tid < 128) { sb2[tid] = db2[tid]; sb3[tid] = db3[tid]; sw4[tid] = dW4[tid]; }
    }
    __syncthreads();

    float* sc = ssc + w*(16*SPD);
    int r = lane >> 1, ch = (lane & 1)*8;

    wmma::fragment<wmma::accumulator,16,16,16,float> acc[8];

#pragma unroll
    for (int f = 0; f < 8; ++f) wmma::fill_fragment(acc[f], 0.0f);
#pragma unroll
    for (int kt = 0; kt < 8; ++kt) {
        wmma::fragment<wmma::matrix_a,16,16,16,__nv_bfloat16,wmma::row_major> af;
        wmma::load_matrix_sync(af, &sA[(w*16)*SP + kt*16], SP);
#pragma unroll
        for (int f = 0; f < 8; ++f) {
            wmma::fragment<wmma::matrix_b,16,16,16,__nv_bfloat16,wmma::row_major> bf;
            wmma::load_matrix_sync(bf, &sW2[(kt*16)*SP + f*16], SP);
            wmma::mma_sync(acc[f], af, bf, acc[f]);
        }
    }
#pragma unroll
    for (int f = 0; f < 8; ++f) {
        wmma::store_matrix_sync(sc, acc[f], SPD, wmma::mem_row_major);
        __syncwarp();
        float v[8];
#pragma unroll
        for (int c = 0; c < 8; ++c)
            v[c] = fast_tanh(sc[r*SPD + ch + c] + sb2[f*16 + ch + c]);
        __nv_bfloat162 q0 = __floats2bfloat162_rn(v[0], v[1]);
        __nv_bfloat162 q1 = __floats2bfloat162_rn(v[2], v[3]);
        __nv_bfloat162 q2 = __floats2bfloat162_rn(v[4], v[5]);
        __nv_bfloat162 q3 = __floats2bfloat162_rn(v[6], v[7]);
        uint4 pk; pk.x = *(u32*)&q0; pk.y = *(u32*)&q1; pk.z = *(u32*)&q2; pk.w = *(u32*)&q3;
        *(uint4*)&sA[(w*16 + r)*SP + f*16 + ch] = pk;
        __syncwarp();
    }

#pragma unroll
    for (int f = 0; f < 8; ++f) wmma::fill_fragment(acc[f], 0.0f);
#pragma unroll
    for (int kt = 0; kt < 8; ++kt) {
        wmma::fragment<wmma::matrix_a,16,16,16,__nv_bfloat16,wmma::row_major> af;
        wmma::load_matrix_sync(af, &sA[(w*16)*SP + kt*16], SP);
#pragma unroll
        for (int f = 0; f < 8; ++f) {
            wmma::fragment<wmma::matrix_b,16,16,16,__nv_bfloat16,wmma::row_major> bf;
            wmma::load_matrix_sync(bf, &sW3[(kt*16)*SP + f*16], SP);
            wmma::mma_sync(acc[f], af, bf, acc[f]);
        }
    }
    float s = 0.0f;
#pragma unroll
    for (int f = 0; f < 8; ++f) {
        wmma::store_matrix_sync(sc, acc[f], SPD, wmma::mem_row_major);
        __syncwarp();
#pragma unroll
        for (int c = 0; c < 8; ++c) {
            int n = f*16 + ch + c;
            s += fast_tanh(sc[r*SPD + ch + c] + sb3[n]) * sw4[n];
        }
        __syncwarp();
    }
    s += __shfl_xor_sync(FULLM, s, 1);

    if ((lane & 1) == 0) {
        int e = blockIdx.x*128 + w*16 + r;
        if (e < NE) {
            s += db4[0];
            int a = e / KNN_K;
            atomicAdd(&g_tf[a*3+0], s * g_nd[e*3+0]);
            atomicAdd(&g_tf[a*3+1], s * g_nd[e*3+1]);
            atomicAdd(&g_tf[a*3+2], s * g_nd[e*3+2]);
        }
    }
}

// ---------------------------------------------------------------------------
// host launcher
// ---------------------------------------------------------------------------
extern "C" void kernel_launch(void* const* d_in, const int* in_sizes, int n_in,
                              void* d_out, int out_size) {
    const float* coords = (const float*)d_in[0];
    const float* node_f = (const float*)d_in[1];
    const float* masses = (const float*)d_in[3];
    const float* vels   = (const float*)d_in[4];
    const float* dW1 = (const float*)d_in[5];
    const float* db1 = (const float*)d_in[6];
    const float* dW2 = (const float*)d_in[7];
    const float* db2 = (const float*)d_in[8];
    const float* dW3 = (const float*)d_in[9];
    const float* db3 = (const float*)d_in[10];
    const float* dW4 = (const float*)d_in[11];
    const float* db4 = (const float*)d_in[12];
    const float* aW1 = (const float*)d_in[13];
    const float* ab1 = (const float*)d_in[14];
    const float* aW2 = (const float*)d_in[15];
    const float* ab2 = (const float*)d_in[16];
    const float* aW3 = (const float*)d_in[17];
    const float* ab3 = (const float*)d_in[18];
    const float* dtp  = (const float*)d_in[20];
    const float* temp = (const float*)d_in[21];
    float* out = (float*)d_out;

    cudaFuncSetAttribute(fused_dist_kernel, cudaFuncAttributeMaxDynamicSharedMemorySize, SM_DIST);
    cudaFuncSetAttribute(combo_kernel,      cudaFuncAttributeMaxDynamicSharedMemorySize, SM_COMBO);

    init_loss_kernel<<<95, 256>>>(coords, vels, temp, dtp, out + (out_size - 1));   // 0
    precompute_kernel<<<dim3(64,3), 256>>>(node_f, dW1, aW1, ab1, dW2, dW3, aW2);   // 1

    for (int s = 0; s < 3; ++s) {
        pos_build_kernel<<<32, 256>>>(dtp, s < 2 ? 1 : 0);                          // 2
        if (s == 2) break;

        combo_kernel<<<NKNNB + NTILE_A, 256, SM_COMBO>>>(aW1, ab2, aW3, ab3);       // 3 <- ncu
        edge_h1_kernel<<<EPAD/8, 256>>>(dW1, db1);
        fused_dist_kernel<<<NTILE_E, 256, SM_DIST>>>(db2, db3, dW4, db4);
        finalize_kernel<<<32, 256>>>(masses, dtp);
    }

    writeout_kernel<<<94, 256>>>(out);
}